// round 4
// baseline (speedup 1.0000x reference)
#include <cuda_runtime.h>
#include <math.h>

typedef unsigned long long u64;

#define HWPIX 9216
#define NPIX 294912
#define CSTRIDE HWPIX
#define BSTRIDE (8*HWPIX)
#define TILE_P 128
#define NTHREADS 512

// smem offsets (floats)
#define OFF_W2 0                      // 128*128
#define OFF_H  (OFF_W2 + 128*128)     // 128*128
#define OFF_W1 (OFF_H + 128*128)      // 4*128
#define OFF_W3 (OFF_W1 + 4*128)       // 8*128 natural [o][k]
#define OFF_B1 (OFF_W3 + 8*128)
#define OFF_B2 (OFF_B1 + 128)
#define OFF_B3 (OFF_B2 + 128)
#define OFF_X  (OFF_B3 + 16)          // 8*128
#define OFF_ST (OFF_X + 8*128)        // 8*128
#define SMEM_FLOATS (OFF_ST + 8*128)  // 36624
#define SMEM_BYTES (SMEM_FLOATS*4)    // 146496

__constant__ int c_CI[4][4] = {{0,1,2,3},{4,5,6,7},{0,2,4,6},{1,3,5,7}};
__constant__ int c_FI[4][4] = {{4,5,6,7},{0,1,2,3},{1,3,5,7},{0,2,4,6}};

__device__ __forceinline__ u64 pk2(float a, float b){
    u64 r; asm("mov.b64 %0,{%1,%2};" : "=l"(r) : "f"(a), "f"(b)); return r;
}
__device__ __forceinline__ void upk2(u64 v, float& a, float& b){
    asm("mov.b64 {%0,%1},%2;" : "=f"(a), "=f"(b) : "l"(v));
}
__device__ __forceinline__ void fma2(u64& d, u64 a, u64 b){
    asm("fma.rn.f32x2 %0,%1,%2,%0;" : "+l"(d) : "l"(a), "l"(b));
}
__device__ __forceinline__ float leaky(float v){ return fmaxf(v, 0.01f * v); }
__device__ __forceinline__ float fast_tanh(float v){
    float e = __expf(2.0f * v);
    return 1.0f - __fdividef(2.0f, e + 1.0f);
}

__global__ void __launch_bounds__(NTHREADS, 1)
realnvp_kernel(const float* __restrict__ x,
               const float* __restrict__ W1, const float* __restrict__ b1,
               const float* __restrict__ W2, const float* __restrict__ b2,
               const float* __restrict__ W3, const float* __restrict__ b3,
               float* __restrict__ out)
{
    extern __shared__ float sm[];
    float* sW2 = sm + OFF_W2;   // [k][o ^ s(k)], s(k)=((k>>2)&7)<<2
    float* sH  = sm + OFF_H;    // [k][p ^ s(k)]
    float* sW1 = sm + OFF_W1;   // [k][m] natural (k<4 -> s=0)
    float* sW3 = sm + OFF_W3;   // [o][k] natural
    float* sB1 = sm + OFF_B1;
    float* sB2 = sm + OFF_B2;
    float* sB3 = sm + OFF_B3;
    float* sX  = sm + OFF_X;    // [c][p] pitch 128
    float* sST = sm + OFF_ST;   // [o][p] pitch 128

    const int tid  = threadIdx.x;
    const int lane = tid & 31, wrp = tid >> 5;
    const int mid_t = (lane & 7) | ((wrp & 3) << 3);   // 0..31
    const int px_t  = (lane >> 3) | ((wrp >> 2) << 2); // 0..15
    const int m0 = mid_t * 4;      // 4 consecutive mids
    const int p0 = px_t * 8;       // 8 consecutive pixels
    const int tm = (mid_t & 7) << 2;  // store swizzle for rows m0..m0+3

    const int gp0 = blockIdx.x * TILE_P;
    const int b   = gp0 / HWPIX;
    const int hw0 = gp0 - b * HWPIX;

    // load x tile [8][128]
    {
        const float* xin = x + (size_t)b * BSTRIDE + hw0;
        int c = tid >> 6, p2 = (tid & 63) << 1;
        *(float2*)&sX[c * 128 + p2] = *(const float2*)&xin[c * CSTRIDE + p2];
    }

    float ld_acc = 0.0f;   // valid for tid < 128

    for (int blk = 0; blk < 8; blk++) {
        const int pat = blk & 3;

        // ---------- stage weights ----------
        {
            const float4* W2g = (const float4*)(W2 + blk * 16384);
            #pragma unroll
            for (int it = 0; it < 8; it++) {
                int v = tid + it * NTHREADS;
                int o = v >> 5, kv = v & 31;        // coalesced LDG
                float4 wv = W2g[v];
                int col = o ^ ((kv & 7) << 2);      // swizzled, rows 4kv..4kv+3
                float* d = sW2 + (kv * 4) * 128 + col;
                d[0] = wv.x; d[128] = wv.y; d[256] = wv.z; d[384] = wv.w;
            }
            if (tid < 128) {
                float4 wv = ((const float4*)(W1 + blk * 512))[tid];
                sW1[0 * 128 + tid] = wv.x;
                sW1[1 * 128 + tid] = wv.y;
                sW1[2 * 128 + tid] = wv.z;
                sW1[3 * 128 + tid] = wv.w;
                sB1[tid] = b1[blk * 128 + tid];
                sB2[tid] = b2[blk * 128 + tid];
            } else if (tid < 384) {
                ((float4*)sW3)[tid - 128] = ((const float4*)(W3 + blk * 1024))[tid - 128];
            } else if (tid < 392) {
                sB3[tid - 384] = b3[blk * 8 + (tid - 384)];
            }
        }
        __syncthreads();

        u64 acc[4][4];   // [px-pair][mid j]

        // ---------- stage 1: h1 = leaky(W1 @ x_fix + b1), K=4 ----------
        #pragma unroll
        for (int j = 0; j < 4; j++) {
            float bb = sB1[m0 + j]; u64 bp = pk2(bb, bb);
            #pragma unroll
            for (int p = 0; p < 4; p++) acc[p][j] = bp;
        }
        #pragma unroll
        for (int k = 0; k < 4; k++) {
            int fc = c_FI[pat][k];
            ulonglong2 ha = *(const ulonglong2*)&sX[fc * 128 + p0];
            ulonglong2 hb = *(const ulonglong2*)&sX[fc * 128 + p0 + 4];
            u64 xp[4] = {ha.x, ha.y, hb.x, hb.y};
            float4 wv = *(const float4*)&sW1[k * 128 + m0];
            u64 wd[4] = {pk2(wv.x,wv.x), pk2(wv.y,wv.y), pk2(wv.z,wv.z), pk2(wv.w,wv.w)};
            #pragma unroll
            for (int p = 0; p < 4; p++)
                #pragma unroll
                for (int j = 0; j < 4; j++) fma2(acc[p][j], xp[p], wd[j]);
        }
        #pragma unroll
        for (int j = 0; j < 4; j++) {
            int r = m0 + j;
            float4 lo, hi;
            upk2(acc[0][j], lo.x, lo.y); upk2(acc[1][j], lo.z, lo.w);
            upk2(acc[2][j], hi.x, hi.y); upk2(acc[3][j], hi.z, hi.w);
            lo.x = leaky(lo.x); lo.y = leaky(lo.y); lo.z = leaky(lo.z); lo.w = leaky(lo.w);
            hi.x = leaky(hi.x); hi.y = leaky(hi.y); hi.z = leaky(hi.z); hi.w = leaky(hi.w);
            *(float4*)&sH[r * 128 + (p0 ^ tm)]       = lo;
            *(float4*)&sH[r * 128 + ((p0 + 4) ^ tm)] = hi;
        }
        __syncthreads();

        // ---------- stage 2: h2 = leaky(W2 @ h1 + b2), K=128 ----------
        #pragma unroll
        for (int j = 0; j < 4; j++) {
            float bb = sB2[m0 + j]; u64 bp = pk2(bb, bb);
            #pragma unroll
            for (int p = 0; p < 4; p++) acc[p][j] = bp;
        }
        #pragma unroll 2
        for (int kk = 0; kk < 32; kk++) {
            const int tk = (kk & 7) << 2;
            const float* hb = sH  + kk * 512;
            const float* wb = sW2 + kk * 512;
            const int hc0 = p0 ^ tk;
            const int hc1 = (p0 + 4) ^ tk;
            const int wc  = m0 ^ tk;
            #pragma unroll
            for (int i = 0; i < 4; i++) {
                ulonglong2 ha = *(const ulonglong2*)(hb + i * 128 + hc0);
                ulonglong2 hv = *(const ulonglong2*)(hb + i * 128 + hc1);
                u64 xp[4] = {ha.x, ha.y, hv.x, hv.y};
                float4 wv = *(const float4*)(wb + i * 128 + wc);
                u64 wd[4] = {pk2(wv.x,wv.x), pk2(wv.y,wv.y), pk2(wv.z,wv.z), pk2(wv.w,wv.w)};
                #pragma unroll
                for (int p = 0; p < 4; p++)
                    #pragma unroll
                    for (int j = 0; j < 4; j++) fma2(acc[p][j], xp[p], wd[j]);
            }
        }
        __syncthreads();   // all h1 reads done before overwrite
        #pragma unroll
        for (int j = 0; j < 4; j++) {
            int r = m0 + j;
            float4 lo, hi;
            upk2(acc[0][j], lo.x, lo.y); upk2(acc[1][j], lo.z, lo.w);
            upk2(acc[2][j], hi.x, hi.y); upk2(acc[3][j], hi.z, hi.w);
            lo.x = leaky(lo.x); lo.y = leaky(lo.y); lo.z = leaky(lo.z); lo.w = leaky(lo.w);
            hi.x = leaky(hi.x); hi.y = leaky(hi.y); hi.z = leaky(hi.z); hi.w = leaky(hi.w);
            *(float4*)&sH[r * 128 + (p0 ^ tm)]       = lo;
            *(float4*)&sH[r * 128 + ((p0 + 4) ^ tm)] = hi;
        }
        __syncthreads();

        // ---------- stage 3: st = tanh(W3 @ h2 + b3) ----------
        {
            int pp = tid & 63;     // pixel pair
            int oq = tid >> 6;     // 0..7, warp-uniform
            float bb = sB3[oq];
            u64 a = pk2(bb, bb);
            const float* w3r = sW3 + oq * 128;
            #pragma unroll 4
            for (int kk = 0; kk < 32; kk++) {
                int col = (2 * pp) ^ ((kk & 7) << 2);
                const float* hb = sH + kk * 512 + col;
                #pragma unroll
                for (int i = 0; i < 4; i++) {
                    u64 hp = *(const u64*)(hb + i * 128);
                    float wv = w3r[kk * 4 + i];
                    fma2(a, hp, pk2(wv, wv));
                }
            }
            float s0, s1; upk2(a, s0, s1);
            *(u64*)&sST[oq * 128 + 2 * pp] = pk2(fast_tanh(s0), fast_tanh(s1));
        }
        __syncthreads();

        // ---------- coupling update + log-det ----------
        if (tid < 128) {
            int p = tid;
            #pragma unroll
            for (int j = 0; j < 4; j++) {
                float s = sST[j * 128 + p];
                float t = sST[(j + 4) * 128 + p];
                int c = c_CI[pat][j];
                float xc = sX[c * 128 + p];
                sX[c * 128 + p] = fmaf(xc, __expf(s), t);
                ld_acc += s;
            }
        }
        __syncthreads();
    }

    // ---------- write results ----------
    {
        float* outx = out + (size_t)b * BSTRIDE + hw0;
        int c = tid >> 6, p2 = (tid & 63) << 1;
        *(float2*)&outx[c * CSTRIDE + p2] = *(const float2*)&sX[c * 128 + p2];
    }
    if (tid < 128) {
        out[(size_t)8 * NPIX + gp0 + tid] = ld_acc;
    }
}

extern "C" void kernel_launch(void* const* d_in, const int* in_sizes, int n_in,
                              void* d_out, int out_size) {
    const float* x  = (const float*)d_in[0];
    const float* W1 = (const float*)d_in[1];
    const float* b1 = (const float*)d_in[2];
    const float* W2 = (const float*)d_in[3];
    const float* b2 = (const float*)d_in[4];
    const float* W3 = (const float*)d_in[5];
    const float* b3 = (const float*)d_in[6];
    float* out = (float*)d_out;

    cudaFuncSetAttribute(realnvp_kernel,
                         cudaFuncAttributeMaxDynamicSharedMemorySize, SMEM_BYTES);

    dim3 grid(NPIX / TILE_P);   // 2304
    dim3 block(NTHREADS);
    realnvp_kernel<<<grid, block, SMEM_BYTES>>>(x, W1, b1, W2, b2, W3, b3, out);
}

// round 8
// speedup vs baseline: 1.1669x; 1.1669x over previous
#include <cuda_runtime.h>
#include <math.h>

typedef unsigned long long u64;

#define HWPIX 9216
#define NPIX 294912
#define CSTRIDE HWPIX
#define BSTRIDE (8*HWPIX)
#define TILE_P 256
#define NTHREADS 512

// smem offsets (floats)
#define OFF_W2 0                      // 128*128
#define OFF_H  (OFF_W2 + 128*128)     // 128*256
#define OFF_W1 (OFF_H + 128*256)      // 4*128
#define OFF_W3 (OFF_W1 + 4*128)       // 8*128 natural [o][k]
#define OFF_B1 (OFF_W3 + 8*128)
#define OFF_B2 (OFF_B1 + 128)
#define OFF_B3 (OFF_B2 + 128)
#define OFF_X  (OFF_B3 + 16)          // 8*256
#define OFF_ST (OFF_X + 8*256)        // 8*256
#define SMEM_FLOATS (OFF_ST + 8*256)  // 55056
#define SMEM_BYTES (SMEM_FLOATS*4)    // 220224

__constant__ int c_CI[4][4] = {{0,1,2,3},{4,5,6,7},{0,2,4,6},{1,3,5,7}};
__constant__ int c_FI[4][4] = {{4,5,6,7},{0,1,2,3},{1,3,5,7},{0,2,4,6}};

__device__ __forceinline__ u64 pk2(float a, float b){
    u64 r; asm("mov.b64 %0,{%1,%2};" : "=l"(r) : "f"(a), "f"(b)); return r;
}
__device__ __forceinline__ void upk2(u64 v, float& a, float& b){
    asm("mov.b64 {%0,%1},%2;" : "=f"(a), "=f"(b) : "l"(v));
}
__device__ __forceinline__ void fma2(u64& d, u64 a, u64 b){
    asm("fma.rn.f32x2 %0,%1,%2,%0;" : "+l"(d) : "l"(a), "l"(b));
}
__device__ __forceinline__ float leaky(float v){ return fmaxf(v, 0.01f * v); }
__device__ __forceinline__ float fast_tanh(float v){
    float e = __expf(2.0f * v);
    return 1.0f - __fdividef(2.0f, e + 1.0f);
}

__global__ void __launch_bounds__(NTHREADS, 1)
realnvp_kernel(const float* __restrict__ x,
               const float* __restrict__ W1, const float* __restrict__ b1,
               const float* __restrict__ W2, const float* __restrict__ b2,
               const float* __restrict__ W3, const float* __restrict__ b3,
               float* __restrict__ out)
{
    extern __shared__ float sm[];
    float* sW2 = sm + OFF_W2;   // [k][o ^ s(k)], s(k)=((k>>2)&7)<<2, pitch 128
    float* sH  = sm + OFF_H;    // [k][p ^ s(k)], same key, pitch 256
    float* sW1 = sm + OFF_W1;   // [k][m] natural, pitch 128
    float* sW3 = sm + OFF_W3;   // [o][k] natural, pitch 128
    float* sB1 = sm + OFF_B1;
    float* sB2 = sm + OFF_B2;
    float* sB3 = sm + OFF_B3;
    float* sX  = sm + OFF_X;    // [c][p] pitch 256
    float* sST = sm + OFF_ST;   // [o][p] pitch 256

    const int tid  = threadIdx.x;
    const int lane = tid & 31, wrp = tid >> 5;
    // lanes 0-7 of each phase: 8 distinct mid groups, same pixel group
    const int mid_t = (lane & 7) | ((wrp & 1) << 3);    // 0..15
    const int px_t  = (lane >> 3) | ((wrp >> 1) << 2);  // 0..31
    const int m0c = mid_t * 4;      // mids m0c..m0c+3 and m0c+64..m0c+67
    const int p0  = px_t * 8;       // 8 consecutive pixels
    const int tm  = (mid_t & 7) << 2;  // store swizzle key (row>>2)&7

    const int gp0 = blockIdx.x * TILE_P;
    const int b   = gp0 / HWPIX;    // 256 | 9216 -> no batch crossing
    const int hw0 = gp0 - b * HWPIX;

    // load x tile [8][256]
    {
        const float* xin = x + (size_t)b * BSTRIDE + hw0;
        int c = tid >> 6, p4 = (tid & 63) << 2;
        *(float4*)&sX[c * 256 + p4] = *(const float4*)&xin[c * CSTRIDE + p4];
    }

    float ld_acc = 0.0f;   // valid for tid < 256

    for (int blk = 0; blk < 8; blk++) {
        const int pat = blk & 3;

        // ---------- stage weights ----------
        {
            const float4* W2g = (const float4*)(W2 + blk * 16384);
            #pragma unroll
            for (int it = 0; it < 8; it++) {
                int v = tid + it * NTHREADS;
                int o = v >> 5, kv = v & 31;        // coalesced LDG
                float4 wv = W2g[v];
                int col = o ^ ((kv & 7) << 2);      // rows 4kv..4kv+3
                float* d = sW2 + (kv * 4) * 128 + col;
                d[0] = wv.x; d[128] = wv.y; d[256] = wv.z; d[384] = wv.w;
            }
            if (tid < 128) {
                float4 wv = ((const float4*)(W1 + blk * 512))[tid];
                sW1[0 * 128 + tid] = wv.x;
                sW1[1 * 128 + tid] = wv.y;
                sW1[2 * 128 + tid] = wv.z;
                sW1[3 * 128 + tid] = wv.w;
                sB1[tid] = b1[blk * 128 + tid];
                sB2[tid] = b2[blk * 128 + tid];
            } else if (tid < 384) {
                ((float4*)sW3)[tid - 128] = ((const float4*)(W3 + blk * 1024))[tid - 128];
            } else if (tid < 392) {
                sB3[tid - 384] = b3[blk * 8 + (tid - 384)];
            }
        }
        __syncthreads();

        u64 acc[4][8];   // [px-pair][mid j]: j<4 -> m0c+j, j>=4 -> m0c+64+j-4

        // ---------- stage 1: h1 = leaky(W1 @ x_fix + b1), K=4 ----------
        #pragma unroll
        for (int j = 0; j < 4; j++) {
            float ba = sB1[m0c + j], bb = sB1[m0c + 64 + j];
            #pragma unroll
            for (int p = 0; p < 4; p++) { acc[p][j] = pk2(ba, ba); acc[p][j+4] = pk2(bb, bb); }
        }
        #pragma unroll
        for (int k = 0; k < 4; k++) {
            int fc = c_FI[pat][k];
            ulonglong2 ha = *(const ulonglong2*)&sX[fc * 256 + p0];
            ulonglong2 hb = *(const ulonglong2*)&sX[fc * 256 + p0 + 4];
            u64 xp[4] = {ha.x, ha.y, hb.x, hb.y};
            float4 wA = *(const float4*)&sW1[k * 128 + m0c];
            float4 wB = *(const float4*)&sW1[k * 128 + m0c + 64];
            u64 wd[8] = {pk2(wA.x,wA.x), pk2(wA.y,wA.y), pk2(wA.z,wA.z), pk2(wA.w,wA.w),
                         pk2(wB.x,wB.x), pk2(wB.y,wB.y), pk2(wB.z,wB.z), pk2(wB.w,wB.w)};
            #pragma unroll
            for (int p = 0; p < 4; p++)
                #pragma unroll
                for (int j = 0; j < 8; j++) fma2(acc[p][j], xp[p], wd[j]);
        }
        #pragma unroll
        for (int j = 0; j < 8; j++) {
            int r = (j < 4) ? (m0c + j) : (m0c + 64 + j - 4);
            float4 lo, hi;
            upk2(acc[0][j], lo.x, lo.y); upk2(acc[1][j], lo.z, lo.w);
            upk2(acc[2][j], hi.x, hi.y); upk2(acc[3][j], hi.z, hi.w);
            lo.x = leaky(lo.x); lo.y = leaky(lo.y); lo.z = leaky(lo.z); lo.w = leaky(lo.w);
            hi.x = leaky(hi.x); hi.y = leaky(hi.y); hi.z = leaky(hi.z); hi.w = leaky(hi.w);
            *(float4*)&sH[r * 256 + (p0 ^ tm)]       = lo;
            *(float4*)&sH[r * 256 + ((p0 + 4) ^ tm)] = hi;
        }
        __syncthreads();

        // ---------- stage 2: h2 = leaky(W2 @ h1 + b2), K=128 ----------
        #pragma unroll
        for (int j = 0; j < 4; j++) {
            float ba = sB2[m0c + j], bb = sB2[m0c + 64 + j];
            #pragma unroll
            for (int p = 0; p < 4; p++) { acc[p][j] = pk2(ba, ba); acc[p][j+4] = pk2(bb, bb); }
        }
        #pragma unroll 2
        for (int kk = 0; kk < 32; kk++) {
            const int tk = (kk & 7) << 2;
            const float* hb = sH  + kk * 4 * 256;
            const float* wb = sW2 + kk * 4 * 128;
            const int hc0 = p0 ^ tk;
            const int hc1 = (p0 + 4) ^ tk;
            const int wc  = m0c ^ tk;
            #pragma unroll
            for (int i = 0; i < 4; i++) {
                ulonglong2 ha = *(const ulonglong2*)(hb + i * 256 + hc0);
                ulonglong2 hv = *(const ulonglong2*)(hb + i * 256 + hc1);
                u64 xp[4] = {ha.x, ha.y, hv.x, hv.y};
                float4 wA = *(const float4*)(wb + i * 128 + wc);
                float4 wB = *(const float4*)(wb + i * 128 + wc + 64);
                u64 wd[8] = {pk2(wA.x,wA.x), pk2(wA.y,wA.y), pk2(wA.z,wA.z), pk2(wA.w,wA.w),
                             pk2(wB.x,wB.x), pk2(wB.y,wB.y), pk2(wB.z,wB.z), pk2(wB.w,wB.w)};
                #pragma unroll
                for (int p = 0; p < 4; p++)
                    #pragma unroll
                    for (int j = 0; j < 8; j++) fma2(acc[p][j], xp[p], wd[j]);
            }
        }
        __syncthreads();   // all h1 reads done before overwrite
        #pragma unroll
        for (int j = 0; j < 8; j++) {
            int r = (j < 4) ? (m0c + j) : (m0c + 64 + j - 4);
            float4 lo, hi;
            upk2(acc[0][j], lo.x, lo.y); upk2(acc[1][j], lo.z, lo.w);
            upk2(acc[2][j], hi.x, hi.y); upk2(acc[3][j], hi.z, hi.w);
            lo.x = leaky(lo.x); lo.y = leaky(lo.y); lo.z = leaky(lo.z); lo.w = leaky(lo.w);
            hi.x = leaky(hi.x); hi.y = leaky(hi.y); hi.z = leaky(hi.z); hi.w = leaky(hi.w);
            *(float4*)&sH[r * 256 + (p0 ^ tm)]       = lo;
            *(float4*)&sH[r * 256 + ((p0 + 4) ^ tm)] = hi;
        }
        __syncthreads();

        // ---------- stage 3: st = tanh(W3 @ h2 + b3) ----------
        {
            int pp = tid & 127;    // pixel pair 0..127
            int oq = tid >> 7;     // 0..3: s-row oq, t-row oq+4 (warp-uniform)
            u64 sa = pk2(sB3[oq], sB3[oq]);
            u64 ta = pk2(sB3[oq + 4], sB3[oq + 4]);
            const float* w3s = sW3 + oq * 128;
            const float* w3t = sW3 + (oq + 4) * 128;
            #pragma unroll 4
            for (int kk = 0; kk < 32; kk++) {
                int col = (2 * pp) ^ ((kk & 7) << 2);
                const float* hb = sH + kk * 4 * 256 + col;
                #pragma unroll
                for (int i = 0; i < 4; i++) {
                    u64 hp = *(const u64*)(hb + i * 256);
                    float ws = w3s[kk * 4 + i];
                    float wt = w3t[kk * 4 + i];
                    fma2(sa, hp, pk2(ws, ws));
                    fma2(ta, hp, pk2(wt, wt));
                }
            }
            float s0, s1, t0, t1;
            upk2(sa, s0, s1); upk2(ta, t0, t1);
            *(u64*)&sST[oq * 256 + 2 * pp]       = pk2(fast_tanh(s0), fast_tanh(s1));
            *(u64*)&sST[(oq + 4) * 256 + 2 * pp] = pk2(fast_tanh(t0), fast_tanh(t1));
        }
        __syncthreads();

        // ---------- coupling update + log-det ----------
        if (tid < 256) {
            int p = tid;
            #pragma unroll
            for (int j = 0; j < 4; j++) {
                float s = sST[j * 256 + p];
                float t = sST[(j + 4) * 256 + p];
                int c = c_CI[pat][j];
                float xc = sX[c * 256 + p];
                sX[c * 256 + p] = fmaf(xc, __expf(s), t);
                ld_acc += s;
            }
        }
        __syncthreads();
    }

    // ---------- write results ----------
    {
        float* outx = out + (size_t)b * BSTRIDE + hw0;
        int c = tid >> 6, p4 = (tid & 63) << 2;
        *(float4*)&outx[c * CSTRIDE + p4] = *(const float4*)&sX[c * 256 + p4];
    }
    if (tid < 256) {
        out[(size_t)8 * NPIX + gp0 + tid] = ld_acc;
    }
}

extern "C" void kernel_launch(void* const* d_in, const int* in_sizes, int n_in,
                              void* d_out, int out_size) {
    const float* x  = (const float*)d_in[0];
    const float* W1 = (const float*)d_in[1];
    const float* b1 = (const float*)d_in[2];
    const float* W2 = (const float*)d_in[3];
    const float* b2 = (const float*)d_in[4];
    const float* W3 = (const float*)d_in[5];
    const float* b3 = (const float*)d_in[6];
    float* out = (float*)d_out;

    cudaFuncSetAttribute(realnvp_kernel,
                         cudaFuncAttributeMaxDynamicSharedMemorySize, SMEM_BYTES);

    dim3 grid(NPIX / TILE_P);   // 1152
    dim3 block(NTHREADS);
    realnvp_kernel<<<grid, block, SMEM_BYTES>>>(x, W1, b1, W2, b2, W3, b3, out);
}

// round 10
// speedup vs baseline: 1.7618x; 1.5098x over previous
#include <cuda_runtime.h>
#include <cuda_bf16.h>
#include <math.h>
#include <stdint.h>

typedef unsigned long long u64;

#define HWPIX 9216
#define NPIX 294912
#define CSTRIDE HWPIX
#define BSTRIDE (8*HWPIX)
#define TILE_P 128
#define NTHREADS 512

// smem byte offsets (bf16 tiles: [128 rows][128 cols], 256B pitch, swizzled)
#define O_AHI 0
#define O_ALO 32768
#define O_BHI 65536
#define O_BLO 98304
#define O_H   131072          // f32 [128][128]
#define O_X   196608          // f32 [8][128]
#define O_ST  200704          // f32 [8][128]
#define O_W1  204800          // f32 [4][128]
#define O_W3  206848          // f32 [8][128]
#define O_B1  210944
#define O_B2  211456
#define O_B3  211968
#define SMEM_BYTES 212032

__constant__ int c_CI[4][4] = {{0,1,2,3},{4,5,6,7},{0,2,4,6},{1,3,5,7}};
__constant__ int c_FI[4][4] = {{4,5,6,7},{0,1,2,3},{1,3,5,7},{0,2,4,6}};

__device__ __forceinline__ u64 pk2(float a, float b){
    u64 r; asm("mov.b64 %0,{%1,%2};" : "=l"(r) : "f"(a), "f"(b)); return r;
}
__device__ __forceinline__ void upk2(u64 v, float& a, float& b){
    asm("mov.b64 {%0,%1},%2;" : "=f"(a), "=f"(b) : "l"(v));
}
__device__ __forceinline__ void fma2(u64& d, u64 a, u64 b){
    asm("fma.rn.f32x2 %0,%1,%2,%0;" : "+l"(d) : "l"(a), "l"(b));
}
__device__ __forceinline__ float leaky(float v){ return fmaxf(v, 0.01f * v); }
__device__ __forceinline__ float fast_tanh(float v){
    float e = __expf(2.0f * v);
    return 1.0f - __fdividef(2.0f, e + 1.0f);
}
__device__ __forceinline__ uint32_t smem_u32(const void* p){
    uint32_t a; asm("{ .reg .u64 t; cvta.to.shared.u64 t, %1; cvt.u32.u64 %0, t; }" : "=r"(a) : "l"(p));
    return a;
}

// swizzled byte offset of (row, col[bf16]) in a [128][128] bf16 tile, 256B pitch.
// XOR the 16B-granule index with (row&7): 8 rows at one column hit 8 distinct banks.
__device__ __forceinline__ uint32_t tofs(int row, int col){
    uint32_t b = ((uint32_t)row << 8) + ((uint32_t)col << 1);
    return b ^ (((uint32_t)row & 7u) << 4);
}

// split 4 f32 into bf16-hi (uint2) and bf16-lo (uint2), memory order f0,f1,f2,f3
__device__ __forceinline__ void split4(float f0, float f1, float f2, float f3,
                                       uint2& hi, uint2& lo){
    uint32_t h01, h23;
    asm("cvt.rn.bf16x2.f32 %0,%1,%2;" : "=r"(h01) : "f"(f1), "f"(f0));
    asm("cvt.rn.bf16x2.f32 %0,%1,%2;" : "=r"(h23) : "f"(f3), "f"(f2));
    float g0 = __uint_as_float(h01 << 16);
    float g1 = __uint_as_float(h01 & 0xFFFF0000u);
    float g2 = __uint_as_float(h23 << 16);
    float g3 = __uint_as_float(h23 & 0xFFFF0000u);
    uint32_t l01, l23;
    asm("cvt.rn.bf16x2.f32 %0,%1,%2;" : "=r"(l01) : "f"(f1 - g1), "f"(f0 - g0));
    asm("cvt.rn.bf16x2.f32 %0,%1,%2;" : "=r"(l23) : "f"(f3 - g3), "f"(f2 - g2));
    hi = make_uint2(h01, h23); lo = make_uint2(l01, l23);
}

__device__ __forceinline__ void ldm4(uint32_t* r, uint32_t addr){
    asm volatile("ldmatrix.sync.aligned.m8n8.x4.shared.b16 {%0,%1,%2,%3}, [%4];"
        : "=r"(r[0]), "=r"(r[1]), "=r"(r[2]), "=r"(r[3]) : "r"(addr));
}
__device__ __forceinline__ void mma16816(float* d, const uint32_t* a, uint32_t b0, uint32_t b1){
    asm volatile("mma.sync.aligned.m16n8k16.row.col.f32.bf16.bf16.f32 "
        "{%0,%1,%2,%3},{%4,%5,%6,%7},{%8,%9},{%0,%1,%2,%3};"
        : "+f"(d[0]), "+f"(d[1]), "+f"(d[2]), "+f"(d[3])
        : "r"(a[0]), "r"(a[1]), "r"(a[2]), "r"(a[3]), "r"(b0), "r"(b1));
}

__global__ void __launch_bounds__(NTHREADS, 1)
realnvp_kernel(const float* __restrict__ x,
               const float* __restrict__ W1, const float* __restrict__ b1,
               const float* __restrict__ W2, const float* __restrict__ b2,
               const float* __restrict__ W3, const float* __restrict__ b3,
               float* __restrict__ out)
{
    extern __shared__ char smem[];
    const uint32_t smb = smem_u32(smem);
    float* sH  = (float*)(smem + O_H);
    float* sX  = (float*)(smem + O_X);
    float* sST = (float*)(smem + O_ST);
    float* sW1 = (float*)(smem + O_W1);
    float* sW3 = (float*)(smem + O_W3);
    float* sB1 = (float*)(smem + O_B1);
    float* sB2 = (float*)(smem + O_B2);
    float* sB3 = (float*)(smem + O_B3);

    const int tid  = threadIdx.x;
    const int lane = tid & 31, wid = tid >> 5;

    // stage-1 mapping: 16 mid-groups x 32 px-groups
    const int mid_t = (lane & 7) | ((wid & 1) << 3);     // 0..15
    const int px_t  = (lane >> 3) | ((wid >> 1) << 2);   // 0..31
    const int m0c = mid_t * 4;     // mids m0c..+3, m0c+64..+67
    const int p0  = px_t * 4;      // 4 px

    // MMA warp tile: 4x4 grid of 32x32
    const int wm = (wid & 3) * 32;
    const int wn = (wid >> 2) * 32;
    // ldmatrix lane addressing
    const int aRow = lane & 15;            // + wm (+16 for second tile)
    const int aCol = (lane >> 4) << 3;     // +k0
    const int bmat = lane >> 3;
    const int bRow = ((bmat >> 1) << 3) + (lane & 7);   // + wn (+16 second)
    const int bCol = (bmat & 1) << 3;                   // +k0

    const int gp0 = blockIdx.x * TILE_P;
    const int b   = gp0 / HWPIX;
    const int hw0 = gp0 - b * HWPIX;

    // load x tile [8][128]
    {
        const float* xin = x + (size_t)b * BSTRIDE + hw0;
        int c = tid >> 6, p2 = (tid & 63) << 1;
        *(float2*)&sX[c * 128 + p2] = *(const float2*)&xin[c * CSTRIDE + p2];
    }

    float ld_acc = 0.0f;   // valid for tid < 128

    for (int blk = 0; blk < 8; blk++) {
        const int pat = blk & 3;

        // ---------- stage weights: W2 -> A_hi/A_lo bf16 tiles [m][k]; W1/W3/b f32 ----------
        {
            const float4* W2g = (const float4*)(W2 + blk * 16384);
            #pragma unroll
            for (int it = 0; it < 8; it++) {
                int v = tid + it * NTHREADS;
                float4 w = W2g[v];
                int m = v >> 5, k0 = (v & 31) << 2;
                uint2 hi, lo;
                split4(w.x, w.y, w.z, w.w, hi, lo);
                uint32_t off = tofs(m, k0);
                *(uint2*)(smem + O_AHI + off) = hi;
                *(uint2*)(smem + O_ALO + off) = lo;
            }
            if (tid < 128) {
                float4 wv = ((const float4*)(W1 + blk * 512))[tid];
                sW1[0 * 128 + tid] = wv.x;
                sW1[1 * 128 + tid] = wv.y;
                sW1[2 * 128 + tid] = wv.z;
                sW1[3 * 128 + tid] = wv.w;
                sB1[tid] = b1[blk * 128 + tid];
                sB2[tid] = b2[blk * 128 + tid];
            } else if (tid < 384) {
                ((float4*)sW3)[tid - 128] = ((const float4*)(W3 + blk * 1024))[tid - 128];
            } else if (tid < 392) {
                sB3[tid - 384] = b3[blk * 8 + (tid - 384)];
            }
        }
        __syncthreads();

        // ---------- stage 1: h1 = leaky(W1 @ x_fix + b1), K=4; split -> B tiles [px][mid] ----------
        {
            float acc[4][8];
            #pragma unroll
            for (int j = 0; j < 4; j++) {
                float ba = sB1[m0c + j], bb = sB1[m0c + 64 + j];
                #pragma unroll
                for (int i = 0; i < 4; i++) { acc[i][j] = ba; acc[i][j + 4] = bb; }
            }
            #pragma unroll
            for (int k = 0; k < 4; k++) {
                int fc = c_FI[pat][k];
                float4 xv = *(const float4*)&sX[fc * 128 + p0];
                float xp[4] = {xv.x, xv.y, xv.z, xv.w};
                float4 wA = *(const float4*)&sW1[k * 128 + m0c];
                float4 wB = *(const float4*)&sW1[k * 128 + m0c + 64];
                float wv[8] = {wA.x, wA.y, wA.z, wA.w, wB.x, wB.y, wB.z, wB.w};
                #pragma unroll
                for (int i = 0; i < 4; i++)
                    #pragma unroll
                    for (int j = 0; j < 8; j++) acc[i][j] = fmaf(xp[i], wv[j], acc[i][j]);
            }
            #pragma unroll
            for (int i = 0; i < 4; i++) {
                int row = p0 + i;
                uint2 hi, lo;
                split4(leaky(acc[i][0]), leaky(acc[i][1]), leaky(acc[i][2]), leaky(acc[i][3]), hi, lo);
                uint32_t offA = tofs(row, m0c);
                *(uint2*)(smem + O_BHI + offA) = hi;
                *(uint2*)(smem + O_BLO + offA) = lo;
                split4(leaky(acc[i][4]), leaky(acc[i][5]), leaky(acc[i][6]), leaky(acc[i][7]), hi, lo);
                uint32_t offB = tofs(row, m0c + 64);
                *(uint2*)(smem + O_BHI + offB) = hi;
                *(uint2*)(smem + O_BLO + offB) = lo;
            }
        }
        __syncthreads();

        // ---------- stage 2: HMMA h2 = W2(hi+lo) @ h1(hi+lo), fp32 accum ----------
        {
            float d[2][4][4];
            #pragma unroll
            for (int mt = 0; mt < 2; mt++)
                #pragma unroll
                for (int nb = 0; nb < 4; nb++)
                    #pragma unroll
                    for (int q = 0; q < 4; q++) d[mt][nb][q] = 0.0f;

            #pragma unroll
            for (int kc = 0; kc < 8; kc++) {
                const int k0 = kc * 16;
                uint32_t ah[2][4], al[2][4], bh[2][4], bl[2][4];
                uint32_t aoff0 = tofs(wm + aRow,      k0 + aCol);
                uint32_t aoff1 = tofs(wm + 16 + aRow, k0 + aCol);
                uint32_t boff0 = tofs(wn + bRow,      k0 + bCol);
                uint32_t boff1 = tofs(wn + 16 + bRow, k0 + bCol);
                ldm4(ah[0], smb + O_AHI + aoff0);
                ldm4(ah[1], smb + O_AHI + aoff1);
                ldm4(bh[0], smb + O_BHI + boff0);
                ldm4(bh[1], smb + O_BHI + boff1);
                ldm4(al[0], smb + O_ALO + aoff0);
                ldm4(al[1], smb + O_ALO + aoff1);
                ldm4(bl[0], smb + O_BLO + boff0);
                ldm4(bl[1], smb + O_BLO + boff1);
                #pragma unroll
                for (int mt = 0; mt < 2; mt++) {
                    #pragma unroll
                    for (int nb = 0; nb < 4; nb++) {
                        uint32_t bhi0 = bh[nb >> 1][(nb & 1) * 2];
                        uint32_t bhi1 = bh[nb >> 1][(nb & 1) * 2 + 1];
                        uint32_t blo0 = bl[nb >> 1][(nb & 1) * 2];
                        uint32_t blo1 = bl[nb >> 1][(nb & 1) * 2 + 1];
                        mma16816(d[mt][nb], ah[mt], bhi0, bhi1);
                        mma16816(d[mt][nb], ah[mt], blo0, blo1);
                        mma16816(d[mt][nb], al[mt], bhi0, bhi1);
                    }
                }
            }

            // epilogue: +b2, leaky, write f32 sH[m][px^key]
            int g = lane >> 2, tg = (lane & 3) * 2;
            #pragma unroll
            for (int mt = 0; mt < 2; mt++) {
                int mr0 = wm + mt * 16 + g;
                int mr1 = mr0 + 8;
                float bv0 = sB2[mr0], bv1 = sB2[mr1];
                int key0 = (mr0 & 7) << 2, key1 = (mr1 & 7) << 2;
                #pragma unroll
                for (int nb = 0; nb < 4; nb++) {
                    int n = wn + nb * 8 + tg;
                    *(u64*)&sH[mr0 * 128 + (n ^ key0)] =
                        pk2(leaky(d[mt][nb][0] + bv0), leaky(d[mt][nb][1] + bv0));
                    *(u64*)&sH[mr1 * 128 + (n ^ key1)] =
                        pk2(leaky(d[mt][nb][2] + bv1), leaky(d[mt][nb][3] + bv1));
                }
            }
        }
        __syncthreads();

        // ---------- stage 3: st = tanh(W3 @ h2 + b3) ----------
        {
            int pp = tid & 63;     // px pair
            int oq = tid >> 6;     // 0..7 output row (warp-uniform)
            float bb = sB3[oq];
            u64 a = pk2(bb, bb);
            const float* w3r = sW3 + oq * 128;
            #pragma unroll 4
            for (int kk = 0; kk < 32; kk++) {
                float4 w = *(const float4*)&w3r[kk * 4];
                float wv[4] = {w.x, w.y, w.z, w.w};
                #pragma unroll
                for (int i = 0; i < 4; i++) {
                    int k = kk * 4 + i;
                    int col = (2 * pp) ^ ((k & 7) << 2);
                    u64 hp = *(const u64*)&sH[k * 128 + col];
                    fma2(a, hp, pk2(wv[i], wv[i]));
                }
            }
            float s0, s1; upk2(a, s0, s1);
            *(u64*)&sST[oq * 128 + 2 * pp] = pk2(fast_tanh(s0), fast_tanh(s1));
        }
        __syncthreads();

        // ---------- coupling update + log-det ----------
        if (tid < 128) {
            int p = tid;
            #pragma unroll
            for (int j = 0; j < 4; j++) {
                float s = sST[j * 128 + p];
                float t = sST[(j + 4) * 128 + p];
                int c = c_CI[pat][j];
                float xc = sX[c * 128 + p];
                sX[c * 128 + p] = fmaf(xc, __expf(s), t);
                ld_acc += s;
            }
        }
        __syncthreads();
    }

    // ---------- write results ----------
    {
        float* outx = out + (size_t)b * BSTRIDE + hw0;
        int c = tid >> 6, p2 = (tid & 63) << 1;
        *(float2*)&outx[c * CSTRIDE + p2] = *(const float2*)&sX[c * 128 + p2];
    }
    if (tid < 128) {
        out[(size_t)8 * NPIX + gp0 + tid] = ld_acc;
    }
}

extern "C" void kernel_launch(void* const* d_in, const int* in_sizes, int n_in,
                              void* d_out, int out_size) {
    const float* x  = (const float*)d_in[0];
    const float* W1 = (const float*)d_in[1];
    const float* b1 = (const float*)d_in[2];
    const float* W2 = (const float*)d_in[3];
    const float* b2 = (const float*)d_in[4];
    const float* W3 = (const float*)d_in[5];
    const float* b3 = (const float*)d_in[6];
    float* out = (float*)d_out;

    cudaFuncSetAttribute(realnvp_kernel,
                         cudaFuncAttributeMaxDynamicSharedMemorySize, SMEM_BYTES);

    dim3 grid(NPIX / TILE_P);   // 2304
    dim3 block(NTHREADS);
    realnvp_kernel<<<grid, block, SMEM_BYTES>>>(x, W1, b1, W2, b2, W3, b3, out);
}

// round 12
// speedup vs baseline: 2.2927x; 1.3013x over previous
#include <cuda_runtime.h>
#include <cuda_bf16.h>
#include <math.h>
#include <stdint.h>

typedef unsigned long long u64;

#define HWPIX 9216
#define NPIX 294912
#define CSTRIDE HWPIX
#define BSTRIDE (8*HWPIX)
#define TILE_P 128
#define NTHREADS 512

// smem byte offsets (bf16 tiles: [128 rows][128 cols], 256B pitch, swizzled)
#define O_AHI 0
#define O_ALO 32768
#define O_BHI 65536           // h1 B tile, then reused as H (h2) hi tile [mid][px]
#define O_BLO 98304
#define O_X   131072          // f32 [8][128]
#define O_STT 135168          // f32 [128 px][8 st]  (ST transposed)
#define O_W1  139264          // f32 [4][128]
#define O_W3H 141312          // bf16 [8][128] swizzled, W3 hi
#define O_W3L 143360          // bf16 [8][128] swizzled, W3 lo
#define O_B1  145408
#define O_B2  145920
#define O_B3  146432
#define SMEM_BYTES 146496

__constant__ int c_CI[4][4] = {{0,1,2,3},{4,5,6,7},{0,2,4,6},{1,3,5,7}};
__constant__ int c_FI[4][4] = {{4,5,6,7},{0,1,2,3},{1,3,5,7},{0,2,4,6}};

__device__ __forceinline__ u64 pk2(float a, float b){
    u64 r; asm("mov.b64 %0,{%1,%2};" : "=l"(r) : "f"(a), "f"(b)); return r;
}
__device__ __forceinline__ float leaky(float v){ return fmaxf(v, 0.01f * v); }
__device__ __forceinline__ float fast_tanh(float v){
    float e = __expf(2.0f * v);
    return 1.0f - __fdividef(2.0f, e + 1.0f);
}
__device__ __forceinline__ uint32_t smem_u32(const void* p){
    uint32_t a; asm("{ .reg .u64 t; cvta.to.shared.u64 t, %1; cvt.u32.u64 %0, t; }" : "=r"(a) : "l"(p));
    return a;
}

// swizzled byte offset of (row, col[bf16]) in a [rows][128] bf16 tile, 256B pitch.
__device__ __forceinline__ uint32_t tofs(int row, int col){
    uint32_t b = ((uint32_t)row << 8) + ((uint32_t)col << 1);
    return b ^ (((uint32_t)row & 7u) << 4);
}

// split 4 f32 into bf16-hi (uint2) and bf16-lo (uint2), memory order f0,f1,f2,f3
__device__ __forceinline__ void split4(float f0, float f1, float f2, float f3,
                                       uint2& hi, uint2& lo){
    uint32_t h01, h23;
    asm("cvt.rn.bf16x2.f32 %0,%1,%2;" : "=r"(h01) : "f"(f1), "f"(f0));
    asm("cvt.rn.bf16x2.f32 %0,%1,%2;" : "=r"(h23) : "f"(f3), "f"(f2));
    float g0 = __uint_as_float(h01 << 16);
    float g1 = __uint_as_float(h01 & 0xFFFF0000u);
    float g2 = __uint_as_float(h23 << 16);
    float g3 = __uint_as_float(h23 & 0xFFFF0000u);
    uint32_t l01, l23;
    asm("cvt.rn.bf16x2.f32 %0,%1,%2;" : "=r"(l01) : "f"(f1 - g1), "f"(f0 - g0));
    asm("cvt.rn.bf16x2.f32 %0,%1,%2;" : "=r"(l23) : "f"(f3 - g3), "f"(f2 - g2));
    hi = make_uint2(h01, h23); lo = make_uint2(l01, l23);
}
// split 2 f32 (memory order v0,v1) into bf16x2 hi and lo words
__device__ __forceinline__ void split2(float v0, float v1, uint32_t& hi, uint32_t& lo){
    asm("cvt.rn.bf16x2.f32 %0,%1,%2;" : "=r"(hi) : "f"(v1), "f"(v0));
    float g0 = __uint_as_float(hi << 16);
    float g1 = __uint_as_float(hi & 0xFFFF0000u);
    asm("cvt.rn.bf16x2.f32 %0,%1,%2;" : "=r"(lo) : "f"(v1 - g1), "f"(v0 - g0));
}

__device__ __forceinline__ void ldm4(uint32_t* r, uint32_t addr){
    asm volatile("ldmatrix.sync.aligned.m8n8.x4.shared.b16 {%0,%1,%2,%3}, [%4];"
        : "=r"(r[0]), "=r"(r[1]), "=r"(r[2]), "=r"(r[3]) : "r"(addr));
}
__device__ __forceinline__ void ldm4t(uint32_t* r, uint32_t addr){
    asm volatile("ldmatrix.sync.aligned.m8n8.x4.trans.shared.b16 {%0,%1,%2,%3}, [%4];"
        : "=r"(r[0]), "=r"(r[1]), "=r"(r[2]), "=r"(r[3]) : "r"(addr));
}
__device__ __forceinline__ void mma16816(float* d, const uint32_t* a, uint32_t b0, uint32_t b1){
    asm volatile("mma.sync.aligned.m16n8k16.row.col.f32.bf16.bf16.f32 "
        "{%0,%1,%2,%3},{%4,%5,%6,%7},{%8,%9},{%0,%1,%2,%3};"
        : "+f"(d[0]), "+f"(d[1]), "+f"(d[2]), "+f"(d[3])
        : "r"(a[0]), "r"(a[1]), "r"(a[2]), "r"(a[3]), "r"(b0), "r"(b1));
}

__global__ void __launch_bounds__(NTHREADS, 1)
realnvp_kernel(const float* __restrict__ x,
               const float* __restrict__ W1, const float* __restrict__ b1,
               const float* __restrict__ W2, const float* __restrict__ b2,
               const float* __restrict__ W3, const float* __restrict__ b3,
               float* __restrict__ out)
{
    extern __shared__ char smem[];
    const uint32_t smb = smem_u32(smem);
    float* sX  = (float*)(smem + O_X);
    float* sTT = (float*)(smem + O_STT);
    float* sW1 = (float*)(smem + O_W1);
    float* sB1 = (float*)(smem + O_B1);
    float* sB2 = (float*)(smem + O_B2);
    float* sB3 = (float*)(smem + O_B3);

    const int tid  = threadIdx.x;
    const int lane = tid & 31, wid = tid >> 5;

    // stage-1 mapping: 16 mid-groups x 32 px-groups
    const int mid_t = (lane & 7) | ((wid & 1) << 3);     // 0..15
    const int px_t  = (lane >> 3) | ((wid >> 1) << 2);   // 0..31
    const int m0c = mid_t * 4;     // mids m0c..+3, m0c+64..+67
    const int p0  = px_t * 4;      // 4 px

    // stage-2 MMA warp tile: 4x4 grid of 32x32
    const int wm = (wid & 3) * 32;
    const int wn = (wid >> 2) * 32;
    const int aRow = lane & 15;
    const int aCol = (lane >> 4) << 3;
    const int bmat = lane >> 3;
    const int bRow = ((bmat >> 1) << 3) + (lane & 7);
    const int bCol = (bmat & 1) << 3;

    const int gp0 = blockIdx.x * TILE_P;
    const int b   = gp0 / HWPIX;
    const int hw0 = gp0 - b * HWPIX;

    // load x tile [8][128]
    {
        const float* xin = x + (size_t)b * BSTRIDE + hw0;
        int c = tid >> 6, p2 = (tid & 63) << 1;
        *(float2*)&sX[c * 128 + p2] = *(const float2*)&xin[c * CSTRIDE + p2];
    }

    float ld_acc = 0.0f;   // valid for tid < 128

    for (int blk = 0; blk < 8; blk++) {
        const int pat = blk & 3;

        // ---------- stage weights: W2 -> A hi/lo; W3 -> bf16 hi/lo tiles; W1/b f32 ----------
        {
            const float4* W2g = (const float4*)(W2 + blk * 16384);
            #pragma unroll
            for (int it = 0; it < 8; it++) {
                int v = tid + it * NTHREADS;
                float4 w = W2g[v];
                int m = v >> 5, k0 = (v & 31) << 2;
                uint2 hi, lo;
                split4(w.x, w.y, w.z, w.w, hi, lo);
                uint32_t off = tofs(m, k0);
                *(uint2*)(smem + O_AHI + off) = hi;
                *(uint2*)(smem + O_ALO + off) = lo;
            }
            if (tid < 128) {
                float4 wv = ((const float4*)(W1 + blk * 512))[tid];
                sW1[0 * 128 + tid] = wv.x;
                sW1[1 * 128 + tid] = wv.y;
                sW1[2 * 128 + tid] = wv.z;
                sW1[3 * 128 + tid] = wv.w;
                sB1[tid] = b1[blk * 128 + tid];
                sB2[tid] = b2[blk * 128 + tid];
            } else if (tid < 384) {
                int v = tid - 128;   // 0..255
                float4 w = ((const float4*)(W3 + blk * 1024))[v];
                int o = v >> 5, k0 = (v & 31) << 2;
                uint2 hi, lo;
                split4(w.x, w.y, w.z, w.w, hi, lo);
                uint32_t off = tofs(o, k0);
                *(uint2*)(smem + O_W3H + off) = hi;
                *(uint2*)(smem + O_W3L + off) = lo;
            } else if (tid < 392) {
                sB3[tid - 384] = b3[blk * 8 + (tid - 384)];
            }
        }
        __syncthreads();

        // ---------- stage 1: h1 = leaky(W1 @ x_fix + b1), K=4; split -> B tiles [px][mid] ----------
        {
            float acc[4][8];
            #pragma unroll
            for (int j = 0; j < 4; j++) {
                float ba = sB1[m0c + j], bb = sB1[m0c + 64 + j];
                #pragma unroll
                for (int i = 0; i < 4; i++) { acc[i][j] = ba; acc[i][j + 4] = bb; }
            }
            #pragma unroll
            for (int k = 0; k < 4; k++) {
                int fc = c_FI[pat][k];
                float4 xv = *(const float4*)&sX[fc * 128 + p0];
                float xp[4] = {xv.x, xv.y, xv.z, xv.w};
                float4 wA = *(const float4*)&sW1[k * 128 + m0c];
                float4 wB = *(const float4*)&sW1[k * 128 + m0c + 64];
                float wv[8] = {wA.x, wA.y, wA.z, wA.w, wB.x, wB.y, wB.z, wB.w};
                #pragma unroll
                for (int i = 0; i < 4; i++)
                    #pragma unroll
                    for (int j = 0; j < 8; j++) acc[i][j] = fmaf(xp[i], wv[j], acc[i][j]);
            }
            #pragma unroll
            for (int i = 0; i < 4; i++) {
                int row = p0 + i;
                uint2 hi, lo;
                split4(leaky(acc[i][0]), leaky(acc[i][1]), leaky(acc[i][2]), leaky(acc[i][3]), hi, lo);
                uint32_t offA = tofs(row, m0c);
                *(uint2*)(smem + O_BHI + offA) = hi;
                *(uint2*)(smem + O_BLO + offA) = lo;
                split4(leaky(acc[i][4]), leaky(acc[i][5]), leaky(acc[i][6]), leaky(acc[i][7]), hi, lo);
                uint32_t offB = tofs(row, m0c + 64);
                *(uint2*)(smem + O_BHI + offB) = hi;
                *(uint2*)(smem + O_BLO + offB) = lo;
            }
        }
        __syncthreads();

        // ---------- stage 2: HMMA h2 = W2(hi+lo) @ h1(hi+lo), fp32 accum ----------
        float d[2][4][4];
        {
            #pragma unroll
            for (int mt = 0; mt < 2; mt++)
                #pragma unroll
                for (int nb = 0; nb < 4; nb++)
                    #pragma unroll
                    for (int q = 0; q < 4; q++) d[mt][nb][q] = 0.0f;

            #pragma unroll
            for (int kc = 0; kc < 8; kc++) {
                const int k0 = kc * 16;
                uint32_t ah[2][4], al[2][4], bh[2][4], bl[2][4];
                uint32_t aoff0 = tofs(wm + aRow,      k0 + aCol);
                uint32_t aoff1 = tofs(wm + 16 + aRow, k0 + aCol);
                uint32_t boff0 = tofs(wn + bRow,      k0 + bCol);
                uint32_t boff1 = tofs(wn + 16 + bRow, k0 + bCol);
                ldm4(ah[0], smb + O_AHI + aoff0);
                ldm4(ah[1], smb + O_AHI + aoff1);
                ldm4(bh[0], smb + O_BHI + boff0);
                ldm4(bh[1], smb + O_BHI + boff1);
                ldm4(al[0], smb + O_ALO + aoff0);
                ldm4(al[1], smb + O_ALO + aoff1);
                ldm4(bl[0], smb + O_BLO + boff0);
                ldm4(bl[1], smb + O_BLO + boff1);
                #pragma unroll
                for (int mt = 0; mt < 2; mt++) {
                    #pragma unroll
                    for (int nb = 0; nb < 4; nb++) {
                        uint32_t bhi0 = bh[nb >> 1][(nb & 1) * 2];
                        uint32_t bhi1 = bh[nb >> 1][(nb & 1) * 2 + 1];
                        uint32_t blo0 = bl[nb >> 1][(nb & 1) * 2];
                        uint32_t blo1 = bl[nb >> 1][(nb & 1) * 2 + 1];
                        mma16816(d[mt][nb], ah[mt], bhi0, bhi1);
                        mma16816(d[mt][nb], ah[mt], blo0, blo1);
                        mma16816(d[mt][nb], al[mt], bhi0, bhi1);
                    }
                }
            }
        }
        __syncthreads();   // all h1 reads done before B-tile buffers are overwritten with H

        // ---------- epilogue: h2 = leaky(D + b2) -> bf16 hi/lo H tiles [mid][px] ----------
        {
            int g = lane >> 2, tg = (lane & 3) * 2;
            #pragma unroll
            for (int mt = 0; mt < 2; mt++) {
                int mr0 = wm + mt * 16 + g;
                int mr1 = mr0 + 8;
                float bv0 = sB2[mr0], bv1 = sB2[mr1];
                #pragma unroll
                for (int nb = 0; nb < 4; nb++) {
                    int n = wn + nb * 8 + tg;
                    uint32_t hi, lo;
                    split2(leaky(d[mt][nb][0] + bv0), leaky(d[mt][nb][1] + bv0), hi, lo);
                    uint32_t o0 = tofs(mr0, n);
                    *(uint32_t*)(smem + O_BHI + o0) = hi;
                    *(uint32_t*)(smem + O_BLO + o0) = lo;
                    split2(leaky(d[mt][nb][2] + bv1), leaky(d[mt][nb][3] + bv1), hi, lo);
                    uint32_t o1 = tofs(mr1, n);
                    *(uint32_t*)(smem + O_BHI + o1) = hi;
                    *(uint32_t*)(smem + O_BLO + o1) = lo;
                }
            }
        }
        __syncthreads();

        // ---------- stage 3 (warps 0-7): ST^T[128px][8st] = tanh(H^T @ W3^T + b3) ----------
        if (wid < 8) {
            const int px0 = wid * 16;
            const int aR = ((lane >> 4) << 3) + (lane & 7);     // mid-row offset
            const int aC = px0 + (((lane >> 3) & 1) << 3);      // px col
            const int bR = lane & 7;                            // st row
            const int bC = (lane >> 3) << 3;                    // k col offset

            float e[4] = {0.f, 0.f, 0.f, 0.f};
            #pragma unroll
            for (int kq = 0; kq < 4; kq++) {
                uint32_t bh[4], bl[4];
                ldm4(bh, smb + O_W3H + tofs(bR, kq * 32 + bC));
                ldm4(bl, smb + O_W3L + tofs(bR, kq * 32 + bC));
                #pragma unroll
                for (int h = 0; h < 2; h++) {
                    int k0 = kq * 32 + h * 16;
                    uint32_t ah[4], al[4];
                    ldm4t(ah, smb + O_BHI + tofs(k0 + aR, aC));
                    ldm4t(al, smb + O_BLO + tofs(k0 + aR, aC));
                    uint32_t b0h = bh[h * 2], b1h = bh[h * 2 + 1];
                    uint32_t b0l = bl[h * 2], b1l = bl[h * 2 + 1];
                    mma16816(e, ah, b0h, b1h);
                    mma16816(e, ah, b0l, b1l);
                    mma16816(e, al, b0h, b1h);
                }
            }
            int g = lane >> 2, c0 = (lane & 3) * 2;
            float bb0 = sB3[c0], bb1 = sB3[c0 + 1];
            *(u64*)&sTT[(px0 + g) * 8 + c0]     = pk2(fast_tanh(e[0] + bb0), fast_tanh(e[1] + bb1));
            *(u64*)&sTT[(px0 + g + 8) * 8 + c0] = pk2(fast_tanh(e[2] + bb0), fast_tanh(e[3] + bb1));
        }
        __syncthreads();

        // ---------- coupling update + log-det ----------
        if (tid < 128) {
            int p = tid;
            float4 sv = *(const float4*)&sTT[p * 8];
            float4 tv = *(const float4*)&sTT[p * 8 + 4];
            float ss[4] = {sv.x, sv.y, sv.z, sv.w};
            float tt[4] = {tv.x, tv.y, tv.z, tv.w};
            #pragma unroll
            for (int j = 0; j < 4; j++) {
                int c = c_CI[pat][j];
                float xc = sX[c * 128 + p];
                sX[c * 128 + p] = fmaf(xc, __expf(ss[j]), tt[j]);
                ld_acc += ss[j];
            }
        }
        __syncthreads();
    }

    // ---------- write results ----------
    {
        float* outx = out + (size_t)b * BSTRIDE + hw0;
        int c = tid >> 6, p2 = (tid & 63) << 1;
        *(float2*)&outx[c * CSTRIDE + p2] = *(const float2*)&sX[c * 128 + p2];
    }
    if (tid < 128) {
        out[(size_t)8 * NPIX + gp0 + tid] = ld_acc;
    }
}

extern "C" void kernel_launch(void* const* d_in, const int* in_sizes, int n_in,
                              void* d_out, int out_size) {
    const float* x  = (const float*)d_in[0];
    const float* W1 = (const float*)d_in[1];
    const float* b1 = (const float*)d_in[2];
    const float* W2 = (const float*)d_in[3];
    const float* b2 = (const float*)d_in[4];
    const float* W3 = (const float*)d_in[5];
    const float* b3 = (const float*)d_in[6];
    float* out = (float*)d_out;

    cudaFuncSetAttribute(realnvp_kernel,
                         cudaFuncAttributeMaxDynamicSharedMemorySize, SMEM_BYTES);

    dim3 grid(NPIX / TILE_P);   // 2304
    dim3 block(NTHREADS);
    realnvp_kernel<<<grid, block, SMEM_BYTES>>>(x, W1, b1, W2, b2, W3, b3, out);
}

// round 15
// speedup vs baseline: 2.3364x; 1.0191x over previous
#include <cuda_runtime.h>
#include <cuda_bf16.h>
#include <math.h>
#include <stdint.h>

typedef unsigned long long u64;

#define HWPIX 9216
#define NPIX 294912
#define CSTRIDE HWPIX
#define BSTRIDE (8*HWPIX)
#define TILE_P 256
#define NTHREADS 512

// smem byte offsets
#define O_AHI 0               // W2 hi bf16 [128m][128k] pitch 256B swizzled (32KB)
#define O_ALO 32768
#define O_BHI 65536           // h1 [256px][128mid] pitch 256B; reused as H [128mid][256px] pitch 512B (64KB)
#define O_BLO 131072
#define O_X   196608          // f32 [8][256] = 8KB
#define O_STT 204800          // f32 [256][8] = 8KB
#define O_W1  212992          // f32 [4][128] = 2KB
#define O_W3H 215040          // bf16 [8][128] swizzled = 2KB
#define O_W3L 217088
#define O_B1  219136
#define O_B2  219648
#define O_B3  220160
#define SMEM_BYTES 220224

__constant__ int c_CI[4][4] = {{0,1,2,3},{4,5,6,7},{0,2,4,6},{1,3,5,7}};
__constant__ int c_FI[4][4] = {{4,5,6,7},{0,1,2,3},{1,3,5,7},{0,2,4,6}};

// pre-split weight scratch (filled once per launch by split_kernel)
__device__ __align__(16) unsigned char g_w2h[8*128*128*2];
__device__ __align__(16) unsigned char g_w2l[8*128*128*2];
__device__ __align__(16) unsigned char g_w3h[8*8*128*2];
__device__ __align__(16) unsigned char g_w3l[8*8*128*2];

__device__ __forceinline__ u64 pk2(float a, float b){
    u64 r; asm("mov.b64 %0,{%1,%2};" : "=l"(r) : "f"(a), "f"(b)); return r;
}
__device__ __forceinline__ float leaky(float v){ return fmaxf(v, 0.01f * v); }
__device__ __forceinline__ float fast_tanh(float v){
    float e = __expf(2.0f * v);
    return 1.0f - __fdividef(2.0f, e + 1.0f);
}
__device__ __forceinline__ uint32_t smem_u32(const void* p){
    uint32_t a; asm("{ .reg .u64 t; cvta.to.shared.u64 t, %1; cvt.u32.u64 %0, t; }" : "=r"(a) : "l"(p));
    return a;
}

// swizzled byte offsets; bank key lives in addr bits [4:7)
__device__ __forceinline__ uint32_t tofsA(int row, int col){   // pitch 256B (128 bf16 cols)
    uint32_t b = ((uint32_t)row << 8) + ((uint32_t)col << 1);
    return b ^ (((uint32_t)row & 7u) << 4);
}
__device__ __forceinline__ uint32_t tofsH(int row, int col){   // pitch 512B (256 bf16 cols)
    uint32_t b = ((uint32_t)row << 9) + ((uint32_t)col << 1);
    return b ^ (((uint32_t)row & 7u) << 4);
}

// split 4 f32 into bf16-hi (uint2) and bf16-lo (uint2), memory order f0..f3
__device__ __forceinline__ void split4(float f0, float f1, float f2, float f3,
                                       uint2& hi, uint2& lo){
    uint32_t h01, h23;
    asm("cvt.rn.bf16x2.f32 %0,%1,%2;" : "=r"(h01) : "f"(f1), "f"(f0));
    asm("cvt.rn.bf16x2.f32 %0,%1,%2;" : "=r"(h23) : "f"(f3), "f"(f2));
    float g0 = __uint_as_float(h01 << 16);
    float g1 = __uint_as_float(h01 & 0xFFFF0000u);
    float g2 = __uint_as_float(h23 << 16);
    float g3 = __uint_as_float(h23 & 0xFFFF0000u);
    uint32_t l01, l23;
    asm("cvt.rn.bf16x2.f32 %0,%1,%2;" : "=r"(l01) : "f"(f1 - g1), "f"(f0 - g0));
    asm("cvt.rn.bf16x2.f32 %0,%1,%2;" : "=r"(l23) : "f"(f3 - g3), "f"(f2 - g2));
    hi = make_uint2(h01, h23); lo = make_uint2(l01, l23);
}
__device__ __forceinline__ void split2(float v0, float v1, uint32_t& hi, uint32_t& lo){
    asm("cvt.rn.bf16x2.f32 %0,%1,%2;" : "=r"(hi) : "f"(v1), "f"(v0));
    float g0 = __uint_as_float(hi << 16);
    float g1 = __uint_as_float(hi & 0xFFFF0000u);
    asm("cvt.rn.bf16x2.f32 %0,%1,%2;" : "=r"(lo) : "f"(v1 - g1), "f"(v0 - g0));
}

__device__ __forceinline__ void ldm4(uint32_t* r, uint32_t addr){
    asm volatile("ldmatrix.sync.aligned.m8n8.x4.shared.b16 {%0,%1,%2,%3}, [%4];"
        : "=r"(r[0]), "=r"(r[1]), "=r"(r[2]), "=r"(r[3]) : "r"(addr));
}
__device__ __forceinline__ void ldm4t(uint32_t* r, uint32_t addr){
    asm volatile("ldmatrix.sync.aligned.m8n8.x4.trans.shared.b16 {%0,%1,%2,%3}, [%4];"
        : "=r"(r[0]), "=r"(r[1]), "=r"(r[2]), "=r"(r[3]) : "r"(addr));
}
__device__ __forceinline__ void mma16816(float* d, const uint32_t* a, uint32_t b0, uint32_t b1){
    asm volatile("mma.sync.aligned.m16n8k16.row.col.f32.bf16.bf16.f32 "
        "{%0,%1,%2,%3},{%4,%5,%6,%7},{%8,%9},{%0,%1,%2,%3};"
        : "+f"(d[0]), "+f"(d[1]), "+f"(d[2]), "+f"(d[3])
        : "r"(a[0]), "r"(a[1]), "r"(a[2]), "r"(a[3]), "r"(b0), "r"(b1));
}

// ---------------- precompute: split W2/W3 into bf16 hi/lo scratch ----------------
__global__ void split_kernel(const float* __restrict__ W2, const float* __restrict__ W3){
    int v = blockIdx.x * blockDim.x + threadIdx.x;
    if (v < 32768) {                       // W2: 8 * 16384 floats / 4
        float4 w = ((const float4*)W2)[v];
        uint2 hi, lo;
        split4(w.x, w.y, w.z, w.w, hi, lo);
        ((uint2*)g_w2h)[v] = hi;
        ((uint2*)g_w2l)[v] = lo;
    } else if (v < 32768 + 2048) {         // W3: 8 * 1024 floats / 4
        int u = v - 32768;
        float4 w = ((const float4*)W3)[u];
        uint2 hi, lo;
        split4(w.x, w.y, w.z, w.w, hi, lo);
        ((uint2*)g_w3h)[u] = hi;
        ((uint2*)g_w3l)[u] = lo;
    }
}

// ---------------- main kernel ----------------
__global__ void __launch_bounds__(NTHREADS, 1)
realnvp_kernel(const float* __restrict__ x,
               const float* __restrict__ W1, const float* __restrict__ b1,
               const float* __restrict__ b2,
               const float* __restrict__ b3,
               float* __restrict__ out)
{
    extern __shared__ char smem[];
    const uint32_t smb = smem_u32(smem);
    float* sX  = (float*)(smem + O_X);
    float* sTT = (float*)(smem + O_STT);
    float* sW1 = (float*)(smem + O_W1);
    float* sB1 = (float*)(smem + O_B1);
    float* sB2 = (float*)(smem + O_B2);
    float* sB3 = (float*)(smem + O_B3);

    const int tid  = threadIdx.x;
    const int lane = tid & 31, wid = tid >> 5;

    // stage-1 mapping: 16 mid-groups x 32 px-groups (8 px each)
    const int mid_t = (lane & 7) | ((wid & 1) << 3);     // 0..15
    const int px_t  = (lane >> 3) | ((wid >> 1) << 2);   // 0..31
    const int m0c = mid_t * 4;
    const int p0  = px_t * 8;

    // stage-2 warp tile: 32m x 64px; 4x4 warp grid
    const int wm = (wid & 3) * 32;
    const int wn = (wid >> 2) * 64;
    const int aRow = lane & 15;
    const int aCol = (lane >> 4) << 3;
    const int bmat = lane >> 3;
    const int bRow = ((bmat >> 1) << 3) + (lane & 7);
    const int bCol = (bmat & 1) << 3;

    const int gp0 = blockIdx.x * TILE_P;
    const int b   = gp0 / HWPIX;            // 256 | 9216
    const int hw0 = gp0 - b * HWPIX;

    // load x tile [8][256]
    {
        const float* xin = x + (size_t)b * BSTRIDE + hw0;
        int c = tid >> 6, p4 = (tid & 63) << 2;
        *(float4*)&sX[c * 256 + p4] = *(const float4*)&xin[c * CSTRIDE + p4];
    }

    float ld_acc = 0.0f;   // valid for tid < 256

    for (int blk = 0; blk < 8; blk++) {
        const int pat = blk & 3;

        // ---------- stage weights: pre-split bf16 LDG -> swizzled STS ----------
        {
            const uint4* w2h = (const uint4*)(g_w2h + blk * 32768);
            const uint4* w2l = (const uint4*)(g_w2l + blk * 32768);
            #pragma unroll
            for (int it = 0; it < 4; it++) {
                int v = tid + it * NTHREADS;         // granule 0..2047
                int m = v >> 4, c0 = (v & 15) << 3;
                uint32_t off = tofsA(m, c0);
                *(uint4*)(smem + O_AHI + off) = w2h[v];
                *(uint4*)(smem + O_ALO + off) = w2l[v];
            }
            if (tid < 128) {
                float4 wv = ((const float4*)(W1 + blk * 512))[tid];
                sW1[0 * 128 + tid] = wv.x;
                sW1[1 * 128 + tid] = wv.y;
                sW1[2 * 128 + tid] = wv.z;
                sW1[3 * 128 + tid] = wv.w;
                sB1[tid] = b1[blk * 128 + tid];
                sB2[tid] = b2[blk * 128 + tid];
            } else if (tid < 256) {
                int v = tid - 128;                   // W3 hi granule
                int m = v >> 4, c0 = (v & 15) << 3;
                *(uint4*)(smem + O_W3H + tofsA(m, c0)) =
                    ((const uint4*)(g_w3h + blk * 2048))[v];
            } else if (tid < 384) {
                int v = tid - 256;                   // W3 lo granule
                int m = v >> 4, c0 = (v & 15) << 3;
                *(uint4*)(smem + O_W3L + tofsA(m, c0)) =
                    ((const uint4*)(g_w3l + blk * 2048))[v];
            } else if (tid < 392) {
                sB3[tid - 384] = b3[blk * 8 + (tid - 384)];
            }
        }
        __syncthreads();

        // ---------- stage 1: h1 = leaky(W1 @ x_fix + b1), K=4; split -> B tiles [px][mid] ----------
        {
            float acc[8][8];
            #pragma unroll
            for (int j = 0; j < 4; j++) {
                float ba = sB1[m0c + j], bb = sB1[m0c + 64 + j];
                #pragma unroll
                for (int i = 0; i < 8; i++) { acc[i][j] = ba; acc[i][j + 4] = bb; }
            }
            #pragma unroll
            for (int k = 0; k < 4; k++) {
                int fc = c_FI[pat][k];
                float4 xv0 = *(const float4*)&sX[fc * 256 + p0];
                float4 xv1 = *(const float4*)&sX[fc * 256 + p0 + 4];
                float xp[8] = {xv0.x, xv0.y, xv0.z, xv0.w, xv1.x, xv1.y, xv1.z, xv1.w};
                float4 wA = *(const float4*)&sW1[k * 128 + m0c];
                float4 wB = *(const float4*)&sW1[k * 128 + m0c + 64];
                float wv[8] = {wA.x, wA.y, wA.z, wA.w, wB.x, wB.y, wB.z, wB.w};
                #pragma unroll
                for (int i = 0; i < 8; i++)
                    #pragma unroll
                    for (int j = 0; j < 8; j++) acc[i][j] = fmaf(xp[i], wv[j], acc[i][j]);
            }
            #pragma unroll
            for (int i = 0; i < 8; i++) {
                int row = p0 + i;
                uint2 hi, lo;
                split4(leaky(acc[i][0]), leaky(acc[i][1]), leaky(acc[i][2]), leaky(acc[i][3]), hi, lo);
                uint32_t offA = tofsA(row, m0c);
                *(uint2*)(smem + O_BHI + offA) = hi;
                *(uint2*)(smem + O_BLO + offA) = lo;
                split4(leaky(acc[i][4]), leaky(acc[i][5]), leaky(acc[i][6]), leaky(acc[i][7]), hi, lo);
                uint32_t offB = tofsA(row, m0c + 64);
                *(uint2*)(smem + O_BHI + offB) = hi;
                *(uint2*)(smem + O_BLO + offB) = lo;
            }
        }
        __syncthreads();

        // ---------- stage 2: HMMA h2 = W2(hi+lo) @ h1(hi+lo), fp32 accum ----------
        float d[2][8][4];
        {
            #pragma unroll
            for (int mt = 0; mt < 2; mt++)
                #pragma unroll
                for (int nb = 0; nb < 8; nb++)
                    #pragma unroll
                    for (int q = 0; q < 4; q++) d[mt][nb][q] = 0.0f;

            // unswizzled bases + per-thread swizzle keys (XOR applied at use:
            // (base + delta) ^ key — col deltas must be added BEFORE the XOR)
            const uint32_t keyA = (uint32_t)(aRow & 7) << 4;
            const uint32_t keyB = (uint32_t)(bRow & 7) << 4;
            const uint32_t ubA0 = ((uint32_t)(wm + aRow)      << 8) + ((uint32_t)aCol << 1);
            const uint32_t ubA1 = ((uint32_t)(wm + 16 + aRow) << 8) + ((uint32_t)aCol << 1);
            uint32_t ubB[4];
            #pragma unroll
            for (int j = 0; j < 4; j++)
                ubB[j] = ((uint32_t)(wn + j * 16 + bRow) << 8) + ((uint32_t)bCol << 1);

            #pragma unroll
            for (int kc = 0; kc < 8; kc++) {
                const uint32_t ko = kc * 32;
                uint32_t ah0[4], ah1[4], al0[4], al1[4];
                uint32_t a0 = (ubA0 + ko) ^ keyA;
                uint32_t a1 = (ubA1 + ko) ^ keyA;
                ldm4(ah0, smb + O_AHI + a0); ldm4(ah1, smb + O_AHI + a1);
                ldm4(al0, smb + O_ALO + a0); ldm4(al1, smb + O_ALO + a1);
                #pragma unroll
                for (int j = 0; j < 4; j++) {
                    uint32_t bo = (ubB[j] + ko) ^ keyB;
                    uint32_t bh[4], bl[4];
                    ldm4(bh, smb + O_BHI + bo);
                    ldm4(bl, smb + O_BLO + bo);
                    #pragma unroll
                    for (int half = 0; half < 2; half++) {
                        int nb = j * 2 + half;
                        uint32_t b0h = bh[half * 2], b1h = bh[half * 2 + 1];
                        uint32_t b0l = bl[half * 2], b1l = bl[half * 2 + 1];
                        mma16816(d[0][nb], ah0, b0h, b1h);
                        mma16816(d[0][nb], ah0, b0l, b1l);
                        mma16816(d[0][nb], al0, b0h, b1h);
                        mma16816(d[1][nb], ah1, b0h, b1h);
                        mma16816(d[1][nb], ah1, b0l, b1l);
                        mma16816(d[1][nb], al1, b0h, b1h);
                    }
                }
            }
        }
        __syncthreads();   // all h1 reads done before buffers are overwritten with H

        // ---------- epilogue: h2 = leaky(D + b2) -> bf16 hi/lo H tiles [mid][px] ----------
        {
            int g = lane >> 2, tg = (lane & 3) * 2;
            #pragma unroll
            for (int mt = 0; mt < 2; mt++) {
                int mr0 = wm + mt * 16 + g;
                int mr1 = mr0 + 8;
                float bv0 = sB2[mr0], bv1 = sB2[mr1];
                #pragma unroll
                for (int nb = 0; nb < 8; nb++) {
                    int n = wn + nb * 8 + tg;
                    uint32_t hi, lo;
                    split2(leaky(d[mt][nb][0] + bv0), leaky(d[mt][nb][1] + bv0), hi, lo);
                    uint32_t o0 = tofsH(mr0, n);
                    *(uint32_t*)(smem + O_BHI + o0) = hi;
                    *(uint32_t*)(smem + O_BLO + o0) = lo;
                    split2(leaky(d[mt][nb][2] + bv1), leaky(d[mt][nb][3] + bv1), hi, lo);
                    uint32_t o1 = tofsH(mr1, n);
                    *(uint32_t*)(smem + O_BHI + o1) = hi;
                    *(uint32_t*)(smem + O_BLO + o1) = lo;
                }
            }
        }
        __syncthreads();

        // ---------- stage 3 (all 16 warps): ST^T[256px][8st] = tanh(H^T @ W3^T + b3) ----------
        {
            const int px0 = wid * 16;
            const int aR = ((lane >> 4) << 3) + (lane & 7);
            const int aC = px0 + (((lane >> 3) & 1) << 3);
            const int bR = lane & 7;
            const int bC = (lane >> 3) << 3;
            // H trans loads: row deltas only (multiples of 16) -> safe to add after XOR
            const uint32_t aBH = smb + O_BHI + tofsH(aR, aC);
            const uint32_t aBL = aBH + (O_BLO - O_BHI);
            // W3 loads: col deltas -> XOR at use
            const uint32_t keyW = (uint32_t)bR << 4;
            const uint32_t ubW  = ((uint32_t)bR << 8) + ((uint32_t)bC << 1);

            float e[4] = {0.f, 0.f, 0.f, 0.f};
            #pragma unroll
            for (int kq = 0; kq < 4; kq++) {
                uint32_t wo = (ubW + kq * 64) ^ keyW;
                uint32_t bh[4], bl[4];
                ldm4(bh, smb + O_W3H + wo);
                ldm4(bl, smb + O_W3L + wo);
                #pragma unroll
                for (int h = 0; h < 2; h++) {
                    uint32_t koff = (uint32_t)(kq * 32 + h * 16) << 9;
                    uint32_t ah[4], al[4];
                    ldm4t(ah, aBH + koff);
                    ldm4t(al, aBL + koff);
                    uint32_t b0h = bh[h * 2], b1h = bh[h * 2 + 1];
                    uint32_t b0l = bl[h * 2], b1l = bl[h * 2 + 1];
                    mma16816(e, ah, b0h, b1h);
                    mma16816(e, ah, b0l, b1l);
                    mma16816(e, al, b0h, b1h);
                }
            }
            int g = lane >> 2, c0 = (lane & 3) * 2;
            float bb0 = sB3[c0], bb1 = sB3[c0 + 1];
            *(u64*)&sTT[(px0 + g) * 8 + c0]     = pk2(fast_tanh(e[0] + bb0), fast_tanh(e[1] + bb1));
            *(u64*)&sTT[(px0 + g + 8) * 8 + c0] = pk2(fast_tanh(e[2] + bb0), fast_tanh(e[3] + bb1));
        }
        __syncthreads();

        // ---------- coupling update + log-det ----------
        if (tid < 256) {
            int p = tid;
            float4 sv = *(const float4*)&sTT[p * 8];
            float4 tv = *(const float4*)&sTT[p * 8 + 4];
            float ss[4] = {sv.x, sv.y, sv.z, sv.w};
            float tt[4] = {tv.x, tv.y, tv.z, tv.w};
            #pragma unroll
            for (int j = 0; j < 4; j++) {
                int c = c_CI[pat][j];
                float xc = sX[c * 256 + p];
                sX[c * 256 + p] = fmaf(xc, __expf(ss[j]), tt[j]);
                ld_acc += ss[j];
            }
        }
        __syncthreads();
    }

    // ---------- write results ----------
    {
        float* outx = out + (size_t)b * BSTRIDE + hw0;
        int c = tid >> 6, p4 = (tid & 63) << 2;
        *(float4*)&outx[c * CSTRIDE + p4] = *(const float4*)&sX[c * 256 + p4];
    }
    if (tid < 256) {
        out[(size_t)8 * NPIX + gp0 + tid] = ld_acc;
    }
}

extern "C" void kernel_launch(void* const* d_in, const int* in_sizes, int n_in,
                              void* d_out, int out_size) {
    const float* x  = (const float*)d_in[0];
    const float* W1 = (const float*)d_in[1];
    const float* b1 = (const float*)d_in[2];
    const float* W2 = (const float*)d_in[3];
    const float* b2 = (const float*)d_in[4];
    const float* W3 = (const float*)d_in[5];
    const float* b3 = (const float*)d_in[6];
    float* out = (float*)d_out;

    cudaFuncSetAttribute(realnvp_kernel,
                         cudaFuncAttributeMaxDynamicSharedMemorySize, SMEM_BYTES);

    split_kernel<<<(34816 + 255) / 256, 256>>>(W2, W3);

    dim3 grid(NPIX / TILE_P);   // 1152
    dim3 block(NTHREADS);
    realnvp_kernel<<<grid, block, SMEM_BYTES>>>(x, W1, b1, b2, b3, out);
}

// round 16
// speedup vs baseline: 2.6089x; 1.1166x over previous
#include <cuda_runtime.h>
#include <cuda_bf16.h>
#include <math.h>
#include <stdint.h>

typedef unsigned long long u64;

#define HWPIX 9216
#define NPIX 294912
#define CSTRIDE HWPIX
#define BSTRIDE (8*HWPIX)
#define TILE_P 128
#define NTHREADS 256

// smem byte offsets
#define O_BHI 0               // h1 [128px][128mid] bf16 pitch 256B; reused as H [128mid][128px]
#define O_BLO 32768
#define O_X   65536           // f32 [8][128] = 4KB
#define O_STT 69632           // f32 [128][8] = 4KB
#define O_W1  73728           // f32 [4][128] = 2KB
#define O_W3H 75776           // bf16 [8][128] swizzled = 2KB
#define O_W3L 77824
#define O_B1  79872
#define O_B2  80384
#define O_B3  80896
#define SMEM_BYTES 80960

__constant__ int c_CI[4][4] = {{0,1,2,3},{4,5,6,7},{0,2,4,6},{1,3,5,7}};
__constant__ int c_FI[4][4] = {{4,5,6,7},{0,1,2,3},{1,3,5,7},{0,2,4,6}};

// W2 pre-split into mma A-fragment order: [blk][mt(8)][kc(8)][lane(32)] x uint4
__device__ __align__(16) unsigned char g_w2fh[8*8*8*32*16];
__device__ __align__(16) unsigned char g_w2fl[8*8*8*32*16];
__device__ __align__(16) unsigned char g_w3h[8*8*128*2];
__device__ __align__(16) unsigned char g_w3l[8*8*128*2];

__device__ __forceinline__ u64 pk2(float a, float b){
    u64 r; asm("mov.b64 %0,{%1,%2};" : "=l"(r) : "f"(a), "f"(b)); return r;
}
__device__ __forceinline__ float leaky(float v){ return fmaxf(v, 0.01f * v); }
__device__ __forceinline__ float fast_tanh(float v){
    float e = __expf(2.0f * v);
    return 1.0f - __fdividef(2.0f, e + 1.0f);
}
__device__ __forceinline__ uint32_t smem_u32(const void* p){
    uint32_t a; asm("{ .reg .u64 t; cvta.to.shared.u64 t, %1; cvt.u32.u64 %0, t; }" : "=r"(a) : "l"(p));
    return a;
}

// swizzled byte offset, [rows][128 bf16] pitch 256B; bank key in addr bits [4:7)
__device__ __forceinline__ uint32_t tofsA(int row, int col){
    uint32_t b = ((uint32_t)row << 8) + ((uint32_t)col << 1);
    return b ^ (((uint32_t)row & 7u) << 4);
}

// split 2 f32 (memory order v0,v1) into bf16x2 hi and lo words
__device__ __forceinline__ void split2(float v0, float v1, uint32_t& hi, uint32_t& lo){
    asm("cvt.rn.bf16x2.f32 %0,%1,%2;" : "=r"(hi) : "f"(v1), "f"(v0));
    float g0 = __uint_as_float(hi << 16);
    float g1 = __uint_as_float(hi & 0xFFFF0000u);
    asm("cvt.rn.bf16x2.f32 %0,%1,%2;" : "=r"(lo) : "f"(v1 - g1), "f"(v0 - g0));
}
// split 4 f32 into bf16-hi (uint2) and bf16-lo (uint2)
__device__ __forceinline__ void split4(float f0, float f1, float f2, float f3,
                                       uint2& hi, uint2& lo){
    uint32_t h01, h23, l01, l23;
    split2(f0, f1, h01, l01);
    split2(f2, f3, h23, l23);
    hi = make_uint2(h01, h23); lo = make_uint2(l01, l23);
}

__device__ __forceinline__ void ldm4(uint32_t* r, uint32_t addr){
    asm volatile("ldmatrix.sync.aligned.m8n8.x4.shared.b16 {%0,%1,%2,%3}, [%4];"
        : "=r"(r[0]), "=r"(r[1]), "=r"(r[2]), "=r"(r[3]) : "r"(addr));
}
__device__ __forceinline__ void ldm4t(uint32_t* r, uint32_t addr){
    asm volatile("ldmatrix.sync.aligned.m8n8.x4.trans.shared.b16 {%0,%1,%2,%3}, [%4];"
        : "=r"(r[0]), "=r"(r[1]), "=r"(r[2]), "=r"(r[3]) : "r"(addr));
}
__device__ __forceinline__ void mma16816(float* d, const uint32_t* a, uint32_t b0, uint32_t b1){
    asm volatile("mma.sync.aligned.m16n8k16.row.col.f32.bf16.bf16.f32 "
        "{%0,%1,%2,%3},{%4,%5,%6,%7},{%8,%9},{%0,%1,%2,%3};"
        : "+f"(d[0]), "+f"(d[1]), "+f"(d[2]), "+f"(d[3])
        : "r"(a[0]), "r"(a[1]), "r"(a[2]), "r"(a[3]), "r"(b0), "r"(b1));
}

// ---------------- precompute: W2 -> fragment-ordered bf16 hi/lo; W3 -> tiles ----------------
__global__ void split_kernel(const float* __restrict__ W2, const float* __restrict__ W3){
    int v = blockIdx.x * blockDim.x + threadIdx.x;
    if (v < 16384) {          // one uint4 pair per (blk, mt, kc, lane)
        int lane = v & 31, kc = (v >> 5) & 7, mt = (v >> 8) & 7, blk = v >> 11;
        const float* Wb = W2 + blk * 16384;
        uint32_t hw[4], lw[4];
        #pragma unroll
        for (int w = 0; w < 4; w++) {
            int row = (lane >> 2) + ((w & 1) << 3);
            int col = (lane & 3) * 2 + ((w >> 1) << 3);
            int m = mt * 16 + row, k0 = kc * 16 + col;
            split2(Wb[m * 128 + k0], Wb[m * 128 + k0 + 1], hw[w], lw[w]);
        }
        ((uint4*)g_w2fh)[v] = make_uint4(hw[0], hw[1], hw[2], hw[3]);
        ((uint4*)g_w2fl)[v] = make_uint4(lw[0], lw[1], lw[2], lw[3]);
    } else if (v < 16384 + 2048) {   // W3: 8*1024 floats / 4
        int u = v - 16384;
        float4 w = ((const float4*)W3)[u];
        uint2 hi, lo;
        split4(w.x, w.y, w.z, w.w, hi, lo);
        ((uint2*)g_w3h)[u] = hi;
        ((uint2*)g_w3l)[u] = lo;
    }
}

// ---------------- main kernel ----------------
__global__ void __launch_bounds__(NTHREADS, 2)
realnvp_kernel(const float* __restrict__ x,
               const float* __restrict__ W1, const float* __restrict__ b1,
               const float* __restrict__ b2,
               const float* __restrict__ b3,
               float* __restrict__ out)
{
    extern __shared__ char smem[];
    const uint32_t smb = smem_u32(smem);
    float* sX  = (float*)(smem + O_X);
    float* sTT = (float*)(smem + O_STT);
    float* sW1 = (float*)(smem + O_W1);
    float* sB1 = (float*)(smem + O_B1);
    float* sB2 = (float*)(smem + O_B2);
    float* sB3 = (float*)(smem + O_B3);

    const int tid  = threadIdx.x;
    const int lane = tid & 31, wid = tid >> 5;   // 8 warps

    // stage-1 mapping: 16 mid-groups x 16 px-groups (8 px each)
    const int mid_t = (lane & 7) | ((wid & 1) << 3);     // 0..15
    const int px_t  = (lane >> 3) | ((wid >> 1) << 2);   // 0..15
    const int m0c = mid_t * 4;
    const int p0  = px_t * 8;

    // stage-2 warp tile: 16m x 128px
    const int wm = wid * 16;
    const int bmat = lane >> 3;
    const int bRow = ((bmat >> 1) << 3) + (lane & 7);
    const int bCol = (bmat & 1) << 3;

    const int gp0 = blockIdx.x * TILE_P;
    const int b   = gp0 / HWPIX;
    const int hw0 = gp0 - b * HWPIX;

    // load x tile [8][128]
    {
        const float* xin = x + (size_t)b * BSTRIDE + hw0;
        int c = tid >> 5, p4 = lane << 2;
        *(float4*)&sX[c * 128 + p4] = *(const float4*)&xin[c * CSTRIDE + p4];
    }

    float ld_acc = 0.0f;   // valid for tid < 128

    for (int blk = 0; blk < 8; blk++) {
        const int pat = blk & 3;

        // ---------- stage small weights (W1, W3 tiles, biases) ----------
        {
            if (tid < 128) {
                float4 wv = ((const float4*)(W1 + blk * 512))[tid];
                sW1[0 * 128 + tid] = wv.x;
                sW1[1 * 128 + tid] = wv.y;
                sW1[2 * 128 + tid] = wv.z;
                sW1[3 * 128 + tid] = wv.w;
                sB1[tid] = b1[blk * 128 + tid];
                sB2[tid] = b2[blk * 128 + tid];
            }
            {   // W3 hi (tid<128) / lo (tid>=128): 128 uint4 granules each
                int v = tid & 127;
                int m = v >> 4, c0 = (v & 15) << 3;
                uint32_t off = tofsA(m, c0);
                if (tid < 128)
                    *(uint4*)(smem + O_W3H + off) = ((const uint4*)(g_w3h + blk * 2048))[v];
                else
                    *(uint4*)(smem + O_W3L + off) = ((const uint4*)(g_w3l + blk * 2048))[v];
            }
            if (tid < 8) sB3[tid] = b3[blk * 8 + tid];
        }
        __syncthreads();

        // ---------- stage 1: h1 = leaky(W1 @ x_fix + b1), K=4; split -> B tiles [px][mid] ----------
        {
            float acc[8][8];
            #pragma unroll
            for (int j = 0; j < 4; j++) {
                float ba = sB1[m0c + j], bb = sB1[m0c + 64 + j];
                #pragma unroll
                for (int i = 0; i < 8; i++) { acc[i][j] = ba; acc[i][j + 4] = bb; }
            }
            #pragma unroll
            for (int k = 0; k < 4; k++) {
                int fc = c_FI[pat][k];
                float4 xv0 = *(const float4*)&sX[fc * 128 + p0];
                float4 xv1 = *(const float4*)&sX[fc * 128 + p0 + 4];
                float xp[8] = {xv0.x, xv0.y, xv0.z, xv0.w, xv1.x, xv1.y, xv1.z, xv1.w};
                float4 wA = *(const float4*)&sW1[k * 128 + m0c];
                float4 wB = *(const float4*)&sW1[k * 128 + m0c + 64];
                float wv[8] = {wA.x, wA.y, wA.z, wA.w, wB.x, wB.y, wB.z, wB.w};
                #pragma unroll
                for (int i = 0; i < 8; i++)
                    #pragma unroll
                    for (int j = 0; j < 8; j++) acc[i][j] = fmaf(xp[i], wv[j], acc[i][j]);
            }
            #pragma unroll
            for (int i = 0; i < 8; i++) {
                int row = p0 + i;
                uint2 hi, lo;
                split4(leaky(acc[i][0]), leaky(acc[i][1]), leaky(acc[i][2]), leaky(acc[i][3]), hi, lo);
                uint32_t offA = tofsA(row, m0c);
                *(uint2*)(smem + O_BHI + offA) = hi;
                *(uint2*)(smem + O_BLO + offA) = lo;
                split4(leaky(acc[i][4]), leaky(acc[i][5]), leaky(acc[i][6]), leaky(acc[i][7]), hi, lo);
                uint32_t offB = tofsA(row, m0c + 64);
                *(uint2*)(smem + O_BHI + offB) = hi;
                *(uint2*)(smem + O_BLO + offB) = lo;
            }
        }
        __syncthreads();

        // ---------- stage 2: HMMA h2 = W2(hi+lo) @ h1(hi+lo); A from fragment LDG ----------
        float d[16][4];
        {
            #pragma unroll
            for (int nb = 0; nb < 16; nb++)
                #pragma unroll
                for (int q = 0; q < 4; q++) d[nb][q] = 0.0f;

            const uint4* aHp = ((const uint4*)g_w2fh) + ((blk * 8 + wid) * 8) * 32 + lane;
            const uint4* aLp = ((const uint4*)g_w2fl) + ((blk * 8 + wid) * 8) * 32 + lane;

            const uint32_t keyB = (uint32_t)(lane & 7) << 4;
            uint32_t ubB[8];
            #pragma unroll
            for (int j = 0; j < 8; j++)
                ubB[j] = ((uint32_t)(j * 16 + bRow) << 8) + ((uint32_t)bCol << 1);

            #pragma unroll
            for (int kc = 0; kc < 8; kc++) {
                const uint32_t ko = kc * 32;
                uint4 hA = aHp[kc * 32];
                uint4 lA = aLp[kc * 32];
                uint32_t ah[4] = {hA.x, hA.y, hA.z, hA.w};
                uint32_t al[4] = {lA.x, lA.y, lA.z, lA.w};
                #pragma unroll
                for (int j = 0; j < 8; j++) {
                    uint32_t bo = (ubB[j] + ko) ^ keyB;
                    uint32_t bh[4], bl[4];
                    ldm4(bh, smb + O_BHI + bo);
                    ldm4(bl, smb + O_BLO + bo);
                    #pragma unroll
                    for (int half = 0; half < 2; half++) {
                        int nb = j * 2 + half;
                        uint32_t b0h = bh[half * 2], b1h = bh[half * 2 + 1];
                        uint32_t b0l = bl[half * 2], b1l = bl[half * 2 + 1];
                        mma16816(d[nb], ah, b0h, b1h);
                        mma16816(d[nb], ah, b0l, b1l);
                        mma16816(d[nb], al, b0h, b1h);
                    }
                }
            }
        }
        __syncthreads();   // all h1 reads done before buffers are overwritten with H

        // ---------- epilogue: h2 = leaky(D + b2) -> bf16 hi/lo H tiles [mid][px] ----------
        {
            int g = lane >> 2, tg = (lane & 3) * 2;
            int mr0 = wm + g, mr1 = wm + 8 + g;
            float bv0 = sB2[mr0], bv1 = sB2[mr1];
            #pragma unroll
            for (int nb = 0; nb < 16; nb++) {
                int n = nb * 8 + tg;
                uint32_t hi, lo;
                split2(leaky(d[nb][0] + bv0), leaky(d[nb][1] + bv0), hi, lo);
                uint32_t o0 = tofsA(mr0, n);
                *(uint32_t*)(smem + O_BHI + o0) = hi;
                *(uint32_t*)(smem + O_BLO + o0) = lo;
                split2(leaky(d[nb][2] + bv1), leaky(d[nb][3] + bv1), hi, lo);
                uint32_t o1 = tofsA(mr1, n);
                *(uint32_t*)(smem + O_BHI + o1) = hi;
                *(uint32_t*)(smem + O_BLO + o1) = lo;
            }
        }
        __syncthreads();

        // ---------- stage 3 (8 warps x 16px): ST^T[128px][8st] = tanh(H^T @ W3^T + b3) ----------
        {
            const int px0 = wid * 16;
            const int aR = ((lane >> 4) << 3) + (lane & 7);
            const int aC = px0 + (((lane >> 3) & 1) << 3);
            const int bR = lane & 7;
            const int bC = (lane >> 3) << 3;
            // H trans loads: row deltas only (multiples of 16 rows = 4096B) -> safe post-XOR
            const uint32_t aBH = smb + O_BHI + tofsA(aR, aC);
            const uint32_t aBL = aBH + (O_BLO - O_BHI);
            // W3 loads: col deltas -> XOR at use
            const uint32_t keyW = (uint32_t)bR << 4;
            const uint32_t ubW  = ((uint32_t)bR << 8) + ((uint32_t)bC << 1);

            float e[4] = {0.f, 0.f, 0.f, 0.f};
            #pragma unroll
            for (int kq = 0; kq < 4; kq++) {
                uint32_t wo = (ubW + kq * 64) ^ keyW;
                uint32_t bh[4], bl[4];
                ldm4(bh, smb + O_W3H + wo);
                ldm4(bl, smb + O_W3L + wo);
                #pragma unroll
                for (int h = 0; h < 2; h++) {
                    uint32_t koff = (uint32_t)(kq * 32 + h * 16) << 8;
                    uint32_t ah[4], al[4];
                    ldm4t(ah, aBH + koff);
                    ldm4t(al, aBL + koff);
                    uint32_t b0h = bh[h * 2], b1h = bh[h * 2 + 1];
                    uint32_t b0l = bl[h * 2], b1l = bl[h * 2 + 1];
                    mma16816(e, ah, b0h, b1h);
                    mma16816(e, ah, b0l, b1l);
                    mma16816(e, al, b0h, b1h);
                }
            }
            int g = lane >> 2, c0 = (lane & 3) * 2;
            float bb0 = sB3[c0], bb1 = sB3[c0 + 1];
            *(u64*)&sTT[(px0 + g) * 8 + c0]     = pk2(fast_tanh(e[0] + bb0), fast_tanh(e[1] + bb1));
            *(u64*)&sTT[(px0 + g + 8) * 8 + c0] = pk2(fast_tanh(e[2] + bb0), fast_tanh(e[3] + bb1));
        }
        __syncthreads();

        // ---------- coupling update + log-det ----------
        if (tid < 128) {
            int p = tid;
            float4 sv = *(const float4*)&sTT[p * 8];
            float4 tv = *(const float4*)&sTT[p * 8 + 4];
            float ss[4] = {sv.x, sv.y, sv.z, sv.w};
            float tt[4] = {tv.x, tv.y, tv.z, tv.w};
            #pragma unroll
            for (int j = 0; j < 4; j++) {
                int c = c_CI[pat][j];
                float xc = sX[c * 128 + p];
                sX[c * 128 + p] = fmaf(xc, __expf(ss[j]), tt[j]);
                ld_acc += ss[j];
            }
        }
        __syncthreads();
    }

    // ---------- write results ----------
    {
        float* outx = out + (size_t)b * BSTRIDE + hw0;
        int c = tid >> 5, p4 = lane << 2;
        *(float4*)&outx[c * CSTRIDE + p4] = *(const float4*)&sX[c * 128 + p4];
    }
    if (tid < 128) {
        out[(size_t)8 * NPIX + gp0 + tid] = ld_acc;
    }
}

extern "C" void kernel_launch(void* const* d_in, const int* in_sizes, int n_in,
                              void* d_out, int out_size) {
    const float* x  = (const float*)d_in[0];
    const float* W1 = (const float*)d_in[1];
    const float* b1 = (const float*)d_in[2];
    const float* W2 = (const float*)d_in[3];
    const float* b2 = (const float*)d_in[4];
    const float* W3 = (const float*)d_in[5];
    const float* b3 = (const float*)d_in[6];
    float* out = (float*)d_out;

    cudaFuncSetAttribute(realnvp_kernel,
                         cudaFuncAttributeMaxDynamicSharedMemorySize, SMEM_BYTES);

    split_kernel<<<(16384 + 2048 + 255) / 256, 256>>>(W2, W3);

    dim3 grid(NPIX / TILE_P);   // 2304
    dim3 block(NTHREADS);
    realnvp_kernel<<<grid, block, SMEM_BYTES>>>(x, W1, b1, b2, b3, out);
}

// round 17
// speedup vs baseline: 2.7479x; 1.0533x over previous
#include <cuda_runtime.h>
#include <cuda_bf16.h>
#include <math.h>
#include <stdint.h>

typedef unsigned long long u64;

#define HWPIX 9216
#define NPIX 294912
#define CSTRIDE HWPIX
#define BSTRIDE (8*HWPIX)
#define TILE_P 128
#define NTHREADS 256

// smem byte offsets
#define O_BHI 0               // h1 [128px][128mid] bf16 pitch 256B; reused as H [128mid][128px]
#define O_BLO 32768
#define O_X   65536           // f32 [8][128] = 4KB
#define O_STT 69632           // f32 [128][8] = 4KB
#define O_W1  73728           // f32 [4][128] = 2KB
#define O_W3H 75776           // bf16 [8][128] swizzled = 2KB
#define O_W3L 77824
#define O_B1  79872
#define O_B2  80384
#define O_B3  80896
#define SMEM_BYTES 80960

__constant__ int c_CI[4][4] = {{0,1,2,3},{4,5,6,7},{0,2,4,6},{1,3,5,7}};
__constant__ int c_FI[4][4] = {{4,5,6,7},{0,1,2,3},{1,3,5,7},{0,2,4,6}};

// W2 pre-split into mma A-fragment order: [blk][mt(8)][kc(8)][lane(32)] x uint4
__device__ __align__(16) unsigned char g_w2fh[8*8*8*32*16];
__device__ __align__(16) unsigned char g_w2fl[8*8*8*32*16];
__device__ __align__(16) unsigned char g_w3h[8*8*128*2];
__device__ __align__(16) unsigned char g_w3l[8*8*128*2];

__device__ __forceinline__ u64 pk2(float a, float b){
    u64 r; asm("mov.b64 %0,{%1,%2};" : "=l"(r) : "f"(a), "f"(b)); return r;
}
__device__ __forceinline__ float leaky(float v){ return fmaxf(v, 0.01f * v); }
__device__ __forceinline__ float fast_tanh(float v){
    float e = __expf(2.0f * v);
    return 1.0f - __fdividef(2.0f, e + 1.0f);
}
__device__ __forceinline__ uint32_t smem_u32(const void* p){
    uint32_t a; asm("{ .reg .u64 t; cvta.to.shared.u64 t, %1; cvt.u32.u64 %0, t; }" : "=r"(a) : "l"(p));
    return a;
}

// swizzled byte offset, [rows][128 bf16] pitch 256B; bank key in addr bits [4:7)
__device__ __forceinline__ uint32_t tofsA(int row, int col){
    uint32_t b = ((uint32_t)row << 8) + ((uint32_t)col << 1);
    return b ^ (((uint32_t)row & 7u) << 4);
}

// split 2 f32 (memory order v0,v1) into bf16x2 hi and lo words
__device__ __forceinline__ void split2(float v0, float v1, uint32_t& hi, uint32_t& lo){
    asm("cvt.rn.bf16x2.f32 %0,%1,%2;" : "=r"(hi) : "f"(v1), "f"(v0));
    float g0 = __uint_as_float(hi << 16);
    float g1 = __uint_as_float(hi & 0xFFFF0000u);
    asm("cvt.rn.bf16x2.f32 %0,%1,%2;" : "=r"(lo) : "f"(v1 - g1), "f"(v0 - g0));
}
// split 4 f32 into bf16-hi (uint2) and bf16-lo (uint2)
__device__ __forceinline__ void split4(float f0, float f1, float f2, float f3,
                                       uint2& hi, uint2& lo){
    uint32_t h01, h23, l01, l23;
    split2(f0, f1, h01, l01);
    split2(f2, f3, h23, l23);
    hi = make_uint2(h01, h23); lo = make_uint2(l01, l23);
}

__device__ __forceinline__ void ldm4(uint32_t* r, uint32_t addr){
    asm volatile("ldmatrix.sync.aligned.m8n8.x4.shared.b16 {%0,%1,%2,%3}, [%4];"
        : "=r"(r[0]), "=r"(r[1]), "=r"(r[2]), "=r"(r[3]) : "r"(addr));
}
__device__ __forceinline__ void ldm4t(uint32_t* r, uint32_t addr){
    asm volatile("ldmatrix.sync.aligned.m8n8.x4.trans.shared.b16 {%0,%1,%2,%3}, [%4];"
        : "=r"(r[0]), "=r"(r[1]), "=r"(r[2]), "=r"(r[3]) : "r"(addr));
}
__device__ __forceinline__ void mma16816(float* d, const uint32_t* a, uint32_t b0, uint32_t b1){
    asm volatile("mma.sync.aligned.m16n8k16.row.col.f32.bf16.bf16.f32 "
        "{%0,%1,%2,%3},{%4,%5,%6,%7},{%8,%9},{%0,%1,%2,%3};"
        : "+f"(d[0]), "+f"(d[1]), "+f"(d[2]), "+f"(d[3])
        : "r"(a[0]), "r"(a[1]), "r"(a[2]), "r"(a[3]), "r"(b0), "r"(b1));
}

// ---------------- precompute: W2 -> fragment-ordered bf16 hi/lo; W3 -> tiles ----------------
__global__ void split_kernel(const float* __restrict__ W2, const float* __restrict__ W3){
    int v = blockIdx.x * blockDim.x + threadIdx.x;
    if (v < 16384) {          // one uint4 pair per (blk, mt, kc, lane)
        int lane = v & 31, kc = (v >> 5) & 7, mt = (v >> 8) & 7, blk = v >> 11;
        const float* Wb = W2 + blk * 16384;
        uint32_t hw[4], lw[4];
        #pragma unroll
        for (int w = 0; w < 4; w++) {
            int row = (lane >> 2) + ((w & 1) << 3);
            int col = (lane & 3) * 2 + ((w >> 1) << 3);
            int m = mt * 16 + row, k0 = kc * 16 + col;
            split2(Wb[m * 128 + k0], Wb[m * 128 + k0 + 1], hw[w], lw[w]);
        }
        ((uint4*)g_w2fh)[v] = make_uint4(hw[0], hw[1], hw[2], hw[3]);
        ((uint4*)g_w2fl)[v] = make_uint4(lw[0], lw[1], lw[2], lw[3]);
    } else if (v < 16384 + 2048) {   // W3: 8*1024 floats / 4
        int u = v - 16384;
        float4 w = ((const float4*)W3)[u];
        uint2 hi, lo;
        split4(w.x, w.y, w.z, w.w, hi, lo);
        ((uint2*)g_w3h)[u] = hi;
        ((uint2*)g_w3l)[u] = lo;
    }
}

// ---------------- main kernel ----------------
__global__ void __launch_bounds__(NTHREADS, 2)
realnvp_kernel(const float* __restrict__ x,
               const float* __restrict__ W1, const float* __restrict__ b1,
               const float* __restrict__ b2,
               const float* __restrict__ b3,
               float* __restrict__ out)
{
    extern __shared__ char smem[];
    const uint32_t smb = smem_u32(smem);
    float* sX  = (float*)(smem + O_X);
    float* sTT = (float*)(smem + O_STT);
    float* sW1 = (float*)(smem + O_W1);
    float* sB1 = (float*)(smem + O_B1);
    float* sB2 = (float*)(smem + O_B2);
    float* sB3 = (float*)(smem + O_B3);

    const int tid  = threadIdx.x;
    const int lane = tid & 31, wid = tid >> 5;   // 8 warps

    // stage-1 mapping: 16 mid-groups x 16 px-groups (8 px each)
    const int mid_t = (lane & 7) | ((wid & 1) << 3);     // 0..15
    const int px_t  = (lane >> 3) | ((wid >> 1) << 2);   // 0..15
    const int m0c = mid_t * 4;
    const int p0  = px_t * 8;

    // stage-2 warp tile: 32m x 64px (4m x 2n warp grid)
    const int wm = (wid & 3) * 32;
    const int wn = (wid >> 2) * 64;
    const int bmat = lane >> 3;
    const int bRow = ((bmat >> 1) << 3) + (lane & 7);
    const int bCol = (bmat & 1) << 3;

    const int gp0 = blockIdx.x * TILE_P;
    const int b   = gp0 / HWPIX;
    const int hw0 = gp0 - b * HWPIX;

    // load x tile [8][128]
    {
        const float* xin = x + (size_t)b * BSTRIDE + hw0;
        int c = tid >> 5, p4 = lane << 2;
        *(float4*)&sX[c * 128 + p4] = *(const float4*)&xin[c * CSTRIDE + p4];
    }

    float ld_acc = 0.0f;   // valid for tid < 128

    for (int blk = 0; blk < 8; blk++) {
        const int pat = blk & 3;

        // ---------- stage small weights (W1, W3 tiles, biases) ----------
        {
            if (tid < 128) {
                float4 wv = ((const float4*)(W1 + blk * 512))[tid];
                sW1[0 * 128 + tid] = wv.x;
                sW1[1 * 128 + tid] = wv.y;
                sW1[2 * 128 + tid] = wv.z;
                sW1[3 * 128 + tid] = wv.w;
                sB1[tid] = b1[blk * 128 + tid];
                sB2[tid] = b2[blk * 128 + tid];
            }
            {   // W3 hi (tid<128) / lo (tid>=128): 128 uint4 granules each
                int v = tid & 127;
                int m = v >> 4, c0 = (v & 15) << 3;
                uint32_t off = tofsA(m, c0);
                if (tid < 128)
                    *(uint4*)(smem + O_W3H + off) = ((const uint4*)(g_w3h + blk * 2048))[v];
                else
                    *(uint4*)(smem + O_W3L + off) = ((const uint4*)(g_w3l + blk * 2048))[v];
            }
            if (tid < 8) sB3[tid] = b3[blk * 8 + tid];
        }
        __syncthreads();

        // ---------- stage 1: h1 = leaky(W1 @ x_fix + b1), K=4; split -> B tiles [px][mid] ----------
        {
            float acc[8][8];
            #pragma unroll
            for (int j = 0; j < 4; j++) {
                float ba = sB1[m0c + j], bb = sB1[m0c + 64 + j];
                #pragma unroll
                for (int i = 0; i < 8; i++) { acc[i][j] = ba; acc[i][j + 4] = bb; }
            }
            #pragma unroll
            for (int k = 0; k < 4; k++) {
                int fc = c_FI[pat][k];
                float4 xv0 = *(const float4*)&sX[fc * 128 + p0];
                float4 xv1 = *(const float4*)&sX[fc * 128 + p0 + 4];
                float xp[8] = {xv0.x, xv0.y, xv0.z, xv0.w, xv1.x, xv1.y, xv1.z, xv1.w};
                float4 wA = *(const float4*)&sW1[k * 128 + m0c];
                float4 wB = *(const float4*)&sW1[k * 128 + m0c + 64];
                float wv[8] = {wA.x, wA.y, wA.z, wA.w, wB.x, wB.y, wB.z, wB.w};
                #pragma unroll
                for (int i = 0; i < 8; i++)
                    #pragma unroll
                    for (int j = 0; j < 8; j++) acc[i][j] = fmaf(xp[i], wv[j], acc[i][j]);
            }
            #pragma unroll
            for (int i = 0; i < 8; i++) {
                int row = p0 + i;
                uint2 hi, lo;
                split4(leaky(acc[i][0]), leaky(acc[i][1]), leaky(acc[i][2]), leaky(acc[i][3]), hi, lo);
                uint32_t offA = tofsA(row, m0c);
                *(uint2*)(smem + O_BHI + offA) = hi;
                *(uint2*)(smem + O_BLO + offA) = lo;
                split4(leaky(acc[i][4]), leaky(acc[i][5]), leaky(acc[i][6]), leaky(acc[i][7]), hi, lo);
                uint32_t offB = tofsA(row, m0c + 64);
                *(uint2*)(smem + O_BHI + offB) = hi;
                *(uint2*)(smem + O_BLO + offB) = lo;
            }
        }
        __syncthreads();

        // ---------- stage 2: HMMA h2 = W2(hi+lo) @ h1(hi+lo); A from fragment LDG ----------
        float d[2][8][4];
        {
            #pragma unroll
            for (int mt = 0; mt < 2; mt++)
                #pragma unroll
                for (int nb = 0; nb < 8; nb++)
                    #pragma unroll
                    for (int q = 0; q < 4; q++) d[mt][nb][q] = 0.0f;

            // A fragment pointers for this warp's two m-tiles
            const int mt0 = (wid & 3) * 2;
            const uint4* aH0 = ((const uint4*)g_w2fh) + ((blk * 8 + mt0) * 8) * 32 + lane;
            const uint4* aL0 = ((const uint4*)g_w2fl) + ((blk * 8 + mt0) * 8) * 32 + lane;
            const uint4* aH1 = aH0 + 8 * 32;
            const uint4* aL1 = aL0 + 8 * 32;

            const uint32_t keyB = (uint32_t)(lane & 7) << 4;
            uint32_t ubB[4];
            #pragma unroll
            for (int j = 0; j < 4; j++)
                ubB[j] = ((uint32_t)(wn + j * 16 + bRow) << 8) + ((uint32_t)bCol << 1);

            #pragma unroll
            for (int kc = 0; kc < 8; kc++) {
                const uint32_t ko = kc * 32;
                uint4 hA0 = aH0[kc * 32], lA0 = aL0[kc * 32];
                uint4 hA1 = aH1[kc * 32], lA1 = aL1[kc * 32];
                uint32_t ah0[4] = {hA0.x, hA0.y, hA0.z, hA0.w};
                uint32_t al0[4] = {lA0.x, lA0.y, lA0.z, lA0.w};
                uint32_t ah1[4] = {hA1.x, hA1.y, hA1.z, hA1.w};
                uint32_t al1[4] = {lA1.x, lA1.y, lA1.z, lA1.w};
                #pragma unroll
                for (int j = 0; j < 4; j++) {
                    uint32_t bo = (ubB[j] + ko) ^ keyB;
                    uint32_t bh[4], bl[4];
                    ldm4(bh, smb + O_BHI + bo);
                    ldm4(bl, smb + O_BLO + bo);
                    #pragma unroll
                    for (int half = 0; half < 2; half++) {
                        int nb = j * 2 + half;
                        uint32_t b0h = bh[half * 2], b1h = bh[half * 2 + 1];
                        uint32_t b0l = bl[half * 2], b1l = bl[half * 2 + 1];
                        mma16816(d[0][nb], ah0, b0h, b1h);
                        mma16816(d[0][nb], ah0, b0l, b1l);
                        mma16816(d[0][nb], al0, b0h, b1h);
                        mma16816(d[1][nb], ah1, b0h, b1h);
                        mma16816(d[1][nb], ah1, b0l, b1l);
                        mma16816(d[1][nb], al1, b0h, b1h);
                    }
                }
            }
        }
        __syncthreads();   // all h1 reads done before buffers are overwritten with H

        // ---------- epilogue: h2 = leaky(D + b2) -> bf16 hi/lo H tiles [mid][px] ----------
        {
            int g = lane >> 2, tg = (lane & 3) * 2;
            #pragma unroll
            for (int mt = 0; mt < 2; mt++) {
                int mr0 = wm + mt * 16 + g;
                int mr1 = mr0 + 8;
                float bv0 = sB2[mr0], bv1 = sB2[mr1];
                #pragma unroll
                for (int nb = 0; nb < 8; nb++) {
                    int n = wn + nb * 8 + tg;
                    uint32_t hi, lo;
                    split2(leaky(d[mt][nb][0] + bv0), leaky(d[mt][nb][1] + bv0), hi, lo);
                    uint32_t o0 = tofsA(mr0, n);
                    *(uint32_t*)(smem + O_BHI + o0) = hi;
                    *(uint32_t*)(smem + O_BLO + o0) = lo;
                    split2(leaky(d[mt][nb][2] + bv1), leaky(d[mt][nb][3] + bv1), hi, lo);
                    uint32_t o1 = tofsA(mr1, n);
                    *(uint32_t*)(smem + O_BHI + o1) = hi;
                    *(uint32_t*)(smem + O_BLO + o1) = lo;
                }
            }
        }
        __syncthreads();

        // ---------- stage 3 (8 warps x 16px): ST^T[128px][8st] = tanh(H^T @ W3^T + b3) ----------
        {
            const int px0 = wid * 16;
            const int aR = ((lane >> 4) << 3) + (lane & 7);
            const int aC = px0 + (((lane >> 3) & 1) << 3);
            const int bR = lane & 7;
            const int bC = (lane >> 3) << 3;
            // H trans loads: row deltas only (multiples of 16 rows = 4096B) -> safe post-XOR
            const uint32_t aBH = smb + O_BHI + tofsA(aR, aC);
            const uint32_t aBL = aBH + (O_BLO - O_BHI);
            // W3 loads: col deltas -> XOR at use
            const uint32_t keyW = (uint32_t)bR << 4;
            const uint32_t ubW  = ((uint32_t)bR << 8) + ((uint32_t)bC << 1);

            float e[4] = {0.f, 0.f, 0.f, 0.f};
            #pragma unroll
            for (int kq = 0; kq < 4; kq++) {
                uint32_t wo = (ubW + kq * 64) ^ keyW;
                uint32_t bh[4], bl[4];
                ldm4(bh, smb + O_W3H + wo);
                ldm4(bl, smb + O_W3L + wo);
                #pragma unroll
                for (int h = 0; h < 2; h++) {
                    uint32_t koff = (uint32_t)(kq * 32 + h * 16) << 8;
                    uint32_t ah[4], al[4];
                    ldm4t(ah, aBH + koff);
                    ldm4t(al, aBL + koff);
                    uint32_t b0h = bh[h * 2], b1h = bh[h * 2 + 1];
                    uint32_t b0l = bl[h * 2], b1l = bl[h * 2 + 1];
                    mma16816(e, ah, b0h, b1h);
                    mma16816(e, ah, b0l, b1l);
                    mma16816(e, al, b0h, b1h);
                }
            }
            int g = lane >> 2, c0 = (lane & 3) * 2;
            float bb0 = sB3[c0], bb1 = sB3[c0 + 1];
            *(u64*)&sTT[(px0 + g) * 8 + c0]     = pk2(fast_tanh(e[0] + bb0), fast_tanh(e[1] + bb1));
            *(u64*)&sTT[(px0 + g + 8) * 8 + c0] = pk2(fast_tanh(e[2] + bb0), fast_tanh(e[3] + bb1));
        }
        __syncthreads();

        // ---------- coupling update + log-det ----------
        if (tid < 128) {
            int p = tid;
            float4 sv = *(const float4*)&sTT[p * 8];
            float4 tv = *(const float4*)&sTT[p * 8 + 4];
            float ss[4] = {sv.x, sv.y, sv.z, sv.w};
            float tt[4] = {tv.x, tv.y, tv.z, tv.w};
            #pragma unroll
            for (int j = 0; j < 4; j++) {
                int c = c_CI[pat][j];
                float xc = sX[c * 128 + p];
                sX[c * 128 + p] = fmaf(xc, __expf(ss[j]), tt[j]);
                ld_acc += ss[j];
            }
        }
        __syncthreads();
    }

    // ---------- write results ----------
    {
        float* outx = out + (size_t)b * BSTRIDE + hw0;
        int c = tid >> 5, p4 = lane << 2;
        *(float4*)&outx[c * CSTRIDE + p4] = *(const float4*)&sX[c * 128 + p4];
    }
    if (tid < 128) {
        out[(size_t)8 * NPIX + gp0 + tid] = ld_acc;
    }
}

extern "C" void kernel_launch(void* const* d_in, const int* in_sizes, int n_in,
                              void* d_out, int out_size) {
    const float* x  = (const float*)d_in[0];
    const float* W1 = (const float*)d_in[1];
    const float* b1 = (const float*)d_in[2];
    const float* W2 = (const float*)d_in[3];
    const float* b2 = (const float*)d_in[4];
    const float* W3 = (const float*)d_in[5];
    const float* b3 = (const float*)d_in[6];
    float* out = (float*)d_out;

    cudaFuncSetAttribute(realnvp_kernel,
                         cudaFuncAttributeMaxDynamicSharedMemorySize, SMEM_BYTES);

    split_kernel<<<(16384 + 2048 + 255) / 256, 256>>>(W2, W3);

    dim3 grid(NPIX / TILE_P);   // 2304
    dim3 block(NTHREADS);
    realnvp_kernel<<<grid, block, SMEM_BYTES>>>(x, W1, b1, b2, b3, out);
}